// round 8
// baseline (speedup 1.0000x reference)
#include <cuda_runtime.h>

namespace {
constexpr int B_ = 8, N_ = 1024, DIM = 512, H_ = 8, DH = 64, INNER = 512, G = 64;
constexpr float SCALE = 0.125f;
constexpr float LOG2E = 1.4426950408889634f;
}

// Scratch (device globals — allocation-free rule)
__device__ float g_q[(size_t)G * N_ * DH];
__device__ float g_k[(size_t)G * N_ * DH];
__device__ float g_v[(size_t)G * N_ * DH];
__device__ float g_y[(size_t)B_ * N_ * INNER];
__device__ float g_ml[G * N_];   // log2-domain row max of lidar logits
__device__ float g_isl[G * N_];  // 1 / sum exp2
__device__ float g_w2[DIM * INNER];
__device__ float g_b2[DIM];

// ---------------------------------------------------------------------------
// helpers
// ---------------------------------------------------------------------------
__device__ __forceinline__ float cvt_tf32f(float x) {
    unsigned r;
    asm("cvt.rna.tf32.f32 %0, %1;" : "=r"(r) : "f"(x));
    return __uint_as_float(r);
}
__device__ __forceinline__ float ex2f(float x) {
    float y;
    asm("ex2.approx.f32 %0, %1;" : "=f"(y) : "f"(x));
    return y;
}

__device__ __forceinline__ void mma8(float* d, const unsigned* a, const unsigned* b) {
    asm("mma.sync.aligned.m16n8k8.row.col.f32.tf32.tf32.f32 "
        "{%0,%1,%2,%3}, {%4,%5,%6,%7}, {%8,%9}, {%0,%1,%2,%3};"
        : "+f"(d[0]), "+f"(d[1]), "+f"(d[2]), "+f"(d[3])
        : "r"(a[0]), "r"(a[1]), "r"(a[2]), "r"(a[3]), "r"(b[0]), "r"(b[1]));
}

// Row swizzle: ((r&3)<<1) ^ (r&4). Even -> float2 pairing preserved; spreads
// rows g8 and g8+4 to different banks (stride 40/72 == 8 mod 32).
__device__ __forceinline__ int swz(int r) { return ((r & 3) << 1) ^ (r & 4); }

// Permuted tile mma: pos(c) = 2*(c&3) + ((c&4)>>2), XOR swz(row).
template <int MT, int NT, int WARPS_N, int ASTR, int BSTR>
__device__ __forceinline__ void mma_slab_p(const float* As, const float* Bs,
                                           int warp, int g8, int t4,
                                           float (&acc)[MT][NT][4]) {
    const int wm = warp / WARPS_N, wn = warp % WARPS_N;
    const int po = (2 * t4) ^ swz(g8);
#pragma unroll
    for (int ks = 0; ks < 4; ks++) {
        const int off = ks * 8 + po;
        unsigned af[MT][4], bf[NT][2];
#pragma unroll
        for (int mt = 0; mt < MT; mt++) {
            int r = wm * (MT * 16) + mt * 16 + g8;
            float2 lo = *(const float2*)&As[r * ASTR + off];
            float2 hi = *(const float2*)&As[(r + 8) * ASTR + off];
            af[mt][0] = __float_as_uint(lo.x);
            af[mt][1] = __float_as_uint(hi.x);
            af[mt][2] = __float_as_uint(lo.y);
            af[mt][3] = __float_as_uint(hi.y);
        }
#pragma unroll
        for (int nt = 0; nt < NT; nt++) {
            int n = wn * (NT * 8) + nt * 8 + g8;
            float2 bv = *(const float2*)&Bs[n * BSTR + off];
            bf[nt][0] = __float_as_uint(bv.x);
            bf[nt][1] = __float_as_uint(bv.y);
        }
#pragma unroll
        for (int mt = 0; mt < MT; mt++)
#pragma unroll
            for (int nt = 0; nt < NT; nt++)
                mma8(acc[mt][nt], af[mt], bf[nt]);
    }
}

// PV (K=64): A = Ps (permuted, stride 72), B = Vs (k-major, stride 72).
__device__ __forceinline__ void mma_pv64(const float* Ps_, const float* Vs_,
                                         int warp, int g8, int t4,
                                         float (&acc)[2][2][4]) {
    const int wm = warp >> 2, wn = warp & 3;
    const int po = (2 * t4) ^ swz(g8);
#pragma unroll
    for (int ks = 0; ks < 8; ks++) {
        const int off = ks * 8 + po;
        const int c = ks * 8 + t4;
        unsigned af[2][4], bf[2][2];
#pragma unroll
        for (int mt = 0; mt < 2; mt++) {
            int r = wm * 32 + mt * 16 + g8;
            float2 lo = *(const float2*)&Ps_[r * 72 + off];
            float2 hi = *(const float2*)&Ps_[(r + 8) * 72 + off];
            af[mt][0] = __float_as_uint(lo.x);
            af[mt][1] = __float_as_uint(hi.x);
            af[mt][2] = __float_as_uint(lo.y);
            af[mt][3] = __float_as_uint(hi.y);
        }
#pragma unroll
        for (int nt = 0; nt < 2; nt++) {
            int n = wn * 16 + nt * 8 + g8;
            bf[nt][0] = __float_as_uint(Vs_[c * 72 + n]);
            bf[nt][1] = __float_as_uint(Vs_[(c + 4) * 72 + n]);
        }
#pragma unroll
        for (int mt = 0; mt < 2; mt++)
#pragma unroll
            for (int nt = 0; nt < 2; nt++)
                mma8(acc[mt][nt], af[mt], bf[nt]);
    }
}

// 128x32 tile staging (256 threads).
struct R4T { float4 a[4]; };
__device__ __forceinline__ void ldg4(R4T& r, const float* g, int ld) {
    const int t = threadIdx.x;
    const int rr = t >> 3, c4 = (t & 7) * 4;
#pragma unroll
    for (int p = 0; p < 4; p++)
        r.a[p] = *(const float4*)(g + (size_t)(rr + p * 32) * ld + c4);
}
template <int STR>
__device__ __forceinline__ void sts4p(float* S, const R4T& r, float scale) {
    const int t = threadIdx.x;
    const int rr = t >> 3, c4 = (t & 7) * 4;
    const int start = (c4 & 24) + ((c4 & 4) ? 1 : 0);
#pragma unroll
    for (int p = 0; p < 4; p++) {
        int row = rr + p * 32;
        int sw = swz(row);
        float4 v = r.a[p];
        float* rp = S + row * STR;
        rp[(start + 0) ^ sw] = cvt_tf32f(v.x * scale);
        rp[(start + 2) ^ sw] = cvt_tf32f(v.y * scale);
        rp[(start + 4) ^ sw] = cvt_tf32f(v.z * scale);
        rp[(start + 6) ^ sw] = cvt_tf32f(v.w * scale);
    }
}

// 64x32 tile staging (256 threads).
struct R2T { float4 a[2]; };
__device__ __forceinline__ void ldg2(R2T& r, const float* g, int ld) {
    const int t = threadIdx.x;
    const int rr = t >> 2, c4 = (t & 3) * 4;
    r.a[0] = *(const float4*)(g + (size_t)rr * ld + c4);
    r.a[1] = *(const float4*)(g + (size_t)rr * ld + c4 + 16);
}
template <int STR>
__device__ __forceinline__ void sts2p(float* S, const R2T& r, float scale) {
    const int t = threadIdx.x;
    const int rr = t >> 2;
    const int sw = swz(rr);
    float* rp = S + rr * STR;
#pragma unroll
    for (int p = 0; p < 2; p++) {
        int c = (t & 3) * 4 + p * 16;
        int start = (c & 24) + ((c & 4) ? 1 : 0);
        float4 v = r.a[p];
        rp[(start + 0) ^ sw] = cvt_tf32f(v.x * scale);
        rp[(start + 2) ^ sw] = cvt_tf32f(v.y * scale);
        rp[(start + 4) ^ sw] = cvt_tf32f(v.z * scale);
        rp[(start + 6) ^ sw] = cvt_tf32f(v.w * scale);
    }
}

// ---------------------------------------------------------------------------
// K1: qkv = x @ w_qkv^T  -> head-major q/k/v  (double-buffered)
// ---------------------------------------------------------------------------
__global__ __launch_bounds__(256) void k_qkv(const float* __restrict__ x,
                                             const float* __restrict__ w) {
    __shared__ float As[2][128 * 40], Bs[2][128 * 40];
    const int t = threadIdx.x, warp = t >> 5, lane = t & 31;
    const int g8 = lane >> 2, t4 = lane & 3;
    const int n0 = blockIdx.x * 128, m0 = blockIdx.y * 128;
    float acc[4][4][4] = {};
    R4T ra, rb;
    ldg4(ra, x + (size_t)m0 * DIM, DIM);
    ldg4(rb, w + (size_t)n0 * DIM, DIM);
    sts4p<40>(As[0], ra, 1.f);
    sts4p<40>(Bs[0], rb, 1.f);
    __syncthreads();
    int cur = 0;
    for (int k0 = 32; k0 < DIM; k0 += 32) {
        ldg4(ra, x + (size_t)m0 * DIM + k0, DIM);
        ldg4(rb, w + (size_t)n0 * DIM + k0, DIM);
        mma_slab_p<4, 4, 4, 40, 40>(As[cur], Bs[cur], warp, g8, t4, acc);
        sts4p<40>(As[cur ^ 1], ra, 1.f);
        sts4p<40>(Bs[cur ^ 1], rb, 1.f);
        __syncthreads();
        cur ^= 1;
    }
    mma_slab_p<4, 4, 4, 40, 40>(As[cur], Bs[cur], warp, g8, t4, acc);
    const int wm = warp >> 2, wn = warp & 3;
#pragma unroll
    for (int mt = 0; mt < 4; mt++)
#pragma unroll
        for (int nt = 0; nt < 4; nt++) {
            int col = n0 + wn * 32 + nt * 8 + 2 * t4;
            int part = col >> 9, h = (col >> 6) & 7, d = col & 63;
            float* dst = part == 0 ? g_q : (part == 1 ? g_k : g_v);
#pragma unroll
            for (int half = 0; half < 2; half++) {
                int row = m0 + wm * 64 + mt * 16 + g8 + half * 8;
                int b = row >> 10, n = row & 1023;
                float2 val = half ? make_float2(acc[mt][nt][2], acc[mt][nt][3])
                                  : make_float2(acc[mt][nt][0], acc[mt][nt][1]);
                *(float2*)&dst[((size_t)((b * 8 + h) * 1024 + n)) * 64 + d] = val;
            }
        }
}

// ---------------------------------------------------------------------------
// K2: lidar softmax row stats in log2 domain (A scaled by SCALE*LOG2E).
// ---------------------------------------------------------------------------
__global__ __launch_bounds__(256) void k_lstats(const float* __restrict__ lidar) {
    __shared__ float Ali[2][128 * 40];
    __shared__ float Bs[2][128 * 40];
    __shared__ float red[4][128], bcast[128], mrun[128], srun[128];
    const int t = threadIdx.x, warp = t >> 5, lane = t & 31;
    const int g8 = lane >> 2, t4 = lane & 3;
    const int gidx = blockIdx.y, b = gidx >> 3, h = gidx & 7;
    const int i0 = blockIdx.x * 128;
    const float* base = lidar + (size_t)b * N_ * INNER + h * 64;
    const int wm = warp >> 2, wn = warp & 3;
    {
        R4T r0;
        ldg4(r0, base + (size_t)i0 * INNER, INNER);
        sts4p<40>(Ali[0], r0, SCALE * LOG2E);
        ldg4(r0, base + (size_t)i0 * INNER + 32, INNER);
        sts4p<40>(Ali[1], r0, SCALE * LOG2E);
    }
    if (t < 128) { mrun[t] = -1e30f; srun[t] = 0.f; }
    R4T rb;
    ldg4(rb, base, INNER);
    sts4p<40>(Bs[0], rb, 1.f);
    __syncthreads();
    int cur = 0;
    float acc[4][4][4];
    for (int idx = 0; idx < 16; idx++) {
        const int ks = idx & 1;
        if (ks == 0) {
#pragma unroll
            for (int a = 0; a < 4; a++)
#pragma unroll
                for (int c = 0; c < 4; c++)
#pragma unroll
                    for (int e = 0; e < 4; e++) acc[a][c][e] = 0.f;
        }
        if (idx < 15) {
            int nxt = idx + 1;
            ldg4(rb, base + (size_t)((nxt >> 1) * 128) * INNER + (nxt & 1) * 32,
                 INNER);
        }
        mma_slab_p<4, 4, 4, 40, 40>(Ali[ks], Bs[cur], warp, g8, t4, acc);
        if (idx < 15) sts4p<40>(Bs[cur ^ 1], rb, 1.f);
        __syncthreads();
        cur ^= 1;
        if (ks == 1) {
            float vm[4][2];
#pragma unroll
            for (int mt = 0; mt < 4; mt++) {
                float a0 = -1e30f, a1 = -1e30f;
#pragma unroll
                for (int nt = 0; nt < 4; nt++) {
                    a0 = fmaxf(a0, fmaxf(acc[mt][nt][0], acc[mt][nt][1]));
                    a1 = fmaxf(a1, fmaxf(acc[mt][nt][2], acc[mt][nt][3]));
                }
#pragma unroll
                for (int off = 1; off <= 2; off <<= 1) {
                    a0 = fmaxf(a0, __shfl_xor_sync(~0u, a0, off));
                    a1 = fmaxf(a1, __shfl_xor_sync(~0u, a1, off));
                }
                vm[mt][0] = a0; vm[mt][1] = a1;
            }
            if (t4 == 0)
#pragma unroll
                for (int mt = 0; mt < 4; mt++) {
                    red[wn][wm * 64 + mt * 16 + g8] = vm[mt][0];
                    red[wn][wm * 64 + mt * 16 + g8 + 8] = vm[mt][1];
                }
            __syncthreads();
            if (t < 128) {
                float tm = fmaxf(fmaxf(red[0][t], red[1][t]),
                                 fmaxf(red[2][t], red[3][t]));
                bcast[t] = fmaxf(mrun[t], tm);
            }
            __syncthreads();
            float vs[4][2];
#pragma unroll
            for (int mt = 0; mt < 4; mt++) {
                int r = wm * 64 + mt * 16 + g8;
                float mn0 = bcast[r], mn1 = bcast[r + 8];
                float s0 = 0.f, s1 = 0.f;
#pragma unroll
                for (int nt = 0; nt < 4; nt++) {
                    s0 += ex2f(acc[mt][nt][0] - mn0) + ex2f(acc[mt][nt][1] - mn0);
                    s1 += ex2f(acc[mt][nt][2] - mn1) + ex2f(acc[mt][nt][3] - mn1);
                }
#pragma unroll
                for (int off = 1; off <= 2; off <<= 1) {
                    s0 += __shfl_xor_sync(~0u, s0, off);
                    s1 += __shfl_xor_sync(~0u, s1, off);
                }
                vs[mt][0] = s0; vs[mt][1] = s1;
            }
            __syncthreads();
            if (t4 == 0)
#pragma unroll
                for (int mt = 0; mt < 4; mt++) {
                    red[wn][wm * 64 + mt * 16 + g8] = vs[mt][0];
                    red[wn][wm * 64 + mt * 16 + g8 + 8] = vs[mt][1];
                }
            __syncthreads();
            if (t < 128) {
                float ts = red[0][t] + red[1][t] + red[2][t] + red[3][t];
                float mn = bcast[t];
                srun[t] = srun[t] * ex2f(mrun[t] - mn) + ts;
                mrun[t] = mn;
            }
            __syncthreads();
        }
    }
    if (t < 128) {
        g_ml[gidx * N_ + i0 + t] = mrun[t];
        g_isl[gidx * N_ + i0 + t] = 1.0f / srun[t];
    }
}

// ---------------------------------------------------------------------------
// K3 (flash2): BM=64, BN=64, 2 CTAs/SM. Online softmax in log2 domain.
// ---------------------------------------------------------------------------
__global__ __launch_bounds__(256, 2) void k_flash2(const float* __restrict__ lidar,
                                                   const float* __restrict__ conv_w) {
    extern __shared__ float sm[];
    float* AliL0 = sm;             // 64*40
    float* AliL1 = sm + 2560;
    float* AliQ0 = sm + 5120;
    float* AliQ1 = sm + 7680;
    float* BsBuf = sm + 10240;     // 2 x 64*40
    float* Vs    = sm + 15360;     // 64*72
    float* Ps    = sm + 19968;     // 64*72
    float* mls   = sm + 24576;
    float* isls  = mls + 64;
    float* m_s   = isls + 64;
    float* l_s   = m_s + 64;
    float* al_s  = l_s + 64;
    float* red   = al_s + 64;      // 4*64

    const int t = threadIdx.x, warp = t >> 5, lane = t & 31;
    const int g8 = lane >> 2, t4 = lane & 3;
    const int gidx = blockIdx.y, i0 = blockIdx.x * 64;
    const int b = gidx >> 3, h = gidx & 7;
    const float c0s = conv_w[0] * SCALE * LOG2E;
    const float c1L = conv_w[1] * LOG2E;
    const int wm = warp >> 2, wn = warp & 3;

    if (t < 64) {
        mls[t] = g_ml[gidx * N_ + i0 + t];
        isls[t] = g_isl[gidx * N_ + i0 + t];
        m_s[t] = -1e30f;
        l_s[t] = 0.f;
    }
    const float* lbase = lidar + (size_t)b * N_ * INNER + h * 64;
    const float* qb = g_q + (size_t)gidx * N_ * DH;
    const float* kb = g_k + (size_t)gidx * N_ * DH;
    const float* vb = g_v + (size_t)gidx * N_ * DH;

    R2T rr_;
    ldg2(rr_, lbase + (size_t)i0 * INNER, INNER);      sts2p<40>(AliL0, rr_, SCALE * LOG2E);
    ldg2(rr_, lbase + (size_t)i0 * INNER + 32, INNER); sts2p<40>(AliL1, rr_, SCALE * LOG2E);
    ldg2(rr_, qb + (size_t)i0 * DH, DH);               sts2p<40>(AliQ0, rr_, c0s);
    ldg2(rr_, qb + (size_t)i0 * DH + 32, DH);          sts2p<40>(AliQ1, rr_, c0s);
    ldg2(rr_, lbase, INNER);                           sts2p<40>(BsBuf, rr_, 1.f);
    __syncthreads();

    float acc_o[2][2][4] = {};
    int cur = 0;

    for (int j0 = 0; j0 < N_; j0 += 64) {
        float acc[2][2][4] = {};
        // slab0: lidar k0
        ldg2(rr_, lbase + (size_t)j0 * INNER + 32, INNER);
        mma_slab_p<2, 2, 4, 40, 40>(AliL0, BsBuf + cur * 2560, warp, g8, t4, acc);
        sts2p<40>(BsBuf + (cur ^ 1) * 2560, rr_, 1.f);
        __syncthreads(); cur ^= 1;
        // slab1: lidar k32
        ldg2(rr_, kb + (size_t)j0 * DH, DH);
        mma_slab_p<2, 2, 4, 40, 40>(AliL1, BsBuf + cur * 2560, warp, g8, t4, acc);
        sts2p<40>(BsBuf + (cur ^ 1) * 2560, rr_, 1.f);
        __syncthreads(); cur ^= 1;
        // lidar softmax transform (log2 domain, precomputed stats)
#pragma unroll
        for (int mt = 0; mt < 2; mt++) {
            int r = wm * 32 + mt * 16 + g8;
            float m0v = mls[r], i0v = isls[r] * c1L;
            float m1v = mls[r + 8], i1v = isls[r + 8] * c1L;
#pragma unroll
            for (int nt = 0; nt < 2; nt++) {
                acc[mt][nt][0] = i0v * ex2f(acc[mt][nt][0] - m0v);
                acc[mt][nt][1] = i0v * ex2f(acc[mt][nt][1] - m0v);
                acc[mt][nt][2] = i1v * ex2f(acc[mt][nt][2] - m1v);
                acc[mt][nt][3] = i1v * ex2f(acc[mt][nt][3] - m1v);
            }
        }
        // slab2: qk k0
        ldg2(rr_, kb + (size_t)j0 * DH + 32, DH);
        mma_slab_p<2, 2, 4, 40, 40>(AliQ0, BsBuf + cur * 2560, warp, g8, t4, acc);
        sts2p<40>(BsBuf + (cur ^ 1) * 2560, rr_, 1.f);
        __syncthreads(); cur ^= 1;
        // slab3: qk k32 (+ next-iter B prefetch + V tile)
        ldg2(rr_, lbase + (size_t)((j0 + 64) & (N_ - 1)) * INNER, INNER);
        mma_slab_p<2, 2, 4, 40, 40>(AliQ1, BsBuf + cur * 2560, warp, g8, t4, acc);
        // row max
        {
            float vm[2][2];
#pragma unroll
            for (int mt = 0; mt < 2; mt++) {
                float a0 = -1e30f, a1 = -1e30f;
#pragma unroll
                for (int nt = 0; nt < 2; nt++) {
                    a0 = fmaxf(a0, fmaxf(acc[mt][nt][0], acc[mt][nt][1]));
                    a1 = fmaxf(a1, fmaxf(acc[mt][nt][2], acc[mt][nt][3]));
                }
#pragma unroll
                for (int off = 1; off <= 2; off <<= 1) {
                    a0 = fmaxf(a0, __shfl_xor_sync(~0u, a0, off));
                    a1 = fmaxf(a1, __shfl_xor_sync(~0u, a1, off));
                }
                vm[mt][0] = a0; vm[mt][1] = a1;
            }
            if (t4 == 0)
#pragma unroll
                for (int mt = 0; mt < 2; mt++) {
                    red[wn * 64 + wm * 32 + mt * 16 + g8] = vm[mt][0];
                    red[wn * 64 + wm * 32 + mt * 16 + g8 + 8] = vm[mt][1];
                }
        }
        // V tile -> Vs (k-major, stride 72)
        {
            int jr = t >> 2, dc = (t & 3) * 16;
            const float* src = vb + (size_t)(j0 + jr) * DH + dc;
#pragma unroll
            for (int q = 0; q < 4; q++) {
                float4 v = *(const float4*)(src + q * 4);
                float4 o;
                o.x = cvt_tf32f(v.x); o.y = cvt_tf32f(v.y);
                o.z = cvt_tf32f(v.z); o.w = cvt_tf32f(v.w);
                *(float4*)(Vs + jr * 72 + dc + q * 4) = o;
            }
        }
        sts2p<40>(BsBuf + (cur ^ 1) * 2560, rr_, 1.f);
        __syncthreads(); cur ^= 1;
        // m / alpha update
        if (t < 64) {
            float tm = fmaxf(fmaxf(red[t], red[64 + t]),
                             fmaxf(red[128 + t], red[192 + t]));
            float mo = m_s[t];
            float mn = fmaxf(mo, tm);
            al_s[t] = ex2f(mo - mn);
            m_s[t] = mn;
        }
        __syncthreads();
        // P = exp2(mid - m) -> Ps (permuted), row sums
        {
            const int swp = swz(g8);
            const int pbase = ((2 * t4) & 3) * 2 + ((t4 & 2) ? 1 : 0);
            float vs_[2][2];
#pragma unroll
            for (int mt = 0; mt < 2; mt++) {
                int r = wm * 32 + mt * 16 + g8;
                float mn0 = m_s[r], mn1 = m_s[r + 8];
                float s0 = 0.f, s1 = 0.f;
#pragma unroll
                for (int nt = 0; nt < 2; nt++) {
                    float p0 = ex2f(acc[mt][nt][0] - mn0);
                    float p1 = ex2f(acc[mt][nt][1] - mn0);
                    float p2 = ex2f(acc[mt][nt][2] - mn1);
                    float p3 = ex2f(acc[mt][nt][3] - mn1);
                    s0 += p0 + p1; s1 += p2 + p3;
                    int gp = wn * 16 + nt * 8;
                    float* rowA = Ps + r * 72 + gp;
                    float* rowB = Ps + (r + 8) * 72 + gp;
                    rowA[(pbase + 0) ^ swp] = cvt_tf32f(p0);
                    rowA[(pbase + 2) ^ swp] = cvt_tf32f(p1);
                    rowB[(pbase + 0) ^ swp] = cvt_tf32f(p2);
                    rowB[(pbase + 2) ^ swp] = cvt_tf32f(p3);
                }
#pragma unroll
                for (int off = 1; off <= 2; off <<= 1) {
                    s0 += __shfl_xor_sync(~0u, s0, off);
                    s1 += __shfl_xor_sync(~0u, s1, off);
                }
                vs_[mt][0] = s0; vs_[mt][1] = s1;
            }
            if (t4 == 0)
#pragma unroll
                for (int mt = 0; mt < 2; mt++) {
                    red[wn * 64 + wm * 32 + mt * 16 + g8] = vs_[mt][0];
                    red[wn * 64 + wm * 32 + mt * 16 + g8 + 8] = vs_[mt][1];
                }
        }
        __syncthreads();
        if (t < 64)
            l_s[t] = l_s[t] * al_s[t] +
                     (red[t] + red[64 + t] + red[128 + t] + red[192 + t]);
        // rescale O accumulator
#pragma unroll
        for (int mt = 0; mt < 2; mt++) {
            int r = wm * 32 + mt * 16 + g8;
            float a0 = al_s[r], a1 = al_s[r + 8];
#pragma unroll
            for (int nt = 0; nt < 2; nt++) {
                acc_o[mt][nt][0] *= a0; acc_o[mt][nt][1] *= a0;
                acc_o[mt][nt][2] *= a1; acc_o[mt][nt][3] *= a1;
            }
        }
        mma_pv64(Ps, Vs, warp, g8, t4, acc_o);
    }
    __syncthreads();
    float* yb = g_y + (size_t)b * N_ * INNER + h * 64;
#pragma unroll
    for (int mt = 0; mt < 2; mt++) {
        int r = wm * 32 + mt * 16 + g8;
        float inv0 = 1.0f / l_s[r], inv1 = 1.0f / l_s[r + 8];
#pragma unroll
        for (int nt = 0; nt < 2; nt++) {
            int d = wn * 16 + nt * 8 + 2 * t4;
            int n = i0 + r;
            *(float2*)&yb[(size_t)n * INNER + d] =
                make_float2(acc_o[mt][nt][0] * inv0, acc_o[mt][nt][1] * inv0);
            *(float2*)&yb[(size_t)(n + 8) * INNER + d] =
                make_float2(acc_o[mt][nt][2] * inv1, acc_o[mt][nt][3] * inv1);
        }
    }
}

// ---------------------------------------------------------------------------
// K4: out = y @ W2^T + bias2  (double-buffered)
// ---------------------------------------------------------------------------
__global__ __launch_bounds__(256) void k_out(float* __restrict__ out) {
    __shared__ float As[2][128 * 40], Bs[2][128 * 40];
    const int t = threadIdx.x, warp = t >> 5, lane = t & 31;
    const int g8 = lane >> 2, t4 = lane & 3;
    const int n0 = blockIdx.x * 128, m0 = blockIdx.y * 128;
    float acc[4][4][4] = {};
    R4T ra, rb;
    ldg4(ra, g_y + (size_t)m0 * INNER, INNER);
    ldg4(rb, g_w2 + (size_t)n0 * INNER, INNER);
    sts4p<40>(As[0], ra, 1.f);
    sts4p<40>(Bs[0], rb, 1.f);
    __syncthreads();
    int cur = 0;
    for (int k0 = 32; k0 < INNER; k0 += 32) {
        ldg4(ra, g_y + (size_t)m0 * INNER + k0, INNER);
        ldg4(rb, g_w2 + (size_t)n0 * INNER + k0, INNER);
        mma_slab_p<4, 4, 4, 40, 40>(As[cur], Bs[cur], warp, g8, t4, acc);
        sts4p<40>(As[cur ^ 1], ra, 1.f);
        sts4p<40>(Bs[cur ^ 1], rb, 1.f);
        __syncthreads();
        cur ^= 1;
    }
    mma_slab_p<4, 4, 4, 40, 40>(As[cur], Bs[cur], warp, g8, t4, acc);
    const int wm = warp >> 2, wn = warp & 3;
#pragma unroll
    for (int mt = 0; mt < 4; mt++)
#pragma unroll
        for (int nt = 0; nt < 4; nt++) {
            int col = n0 + wn * 32 + nt * 8 + 2 * t4;
            float b0 = g_b2[col], b1 = g_b2[col + 1];
            int r = m0 + wm * 64 + mt * 16 + g8;
            *(float2*)&out[(size_t)r * DIM + col] =
                make_float2(acc[mt][nt][0] + b0, acc[mt][nt][1] + b1);
            *(float2*)&out[(size_t)(r + 8) * DIM + col] =
                make_float2(acc[mt][nt][2] + b0, acc[mt][nt][3] + b1);
        }
}

// ---------------------------------------------------------------------------
// Precompute: W2 = Wout(.,h-block) @ Wm ; bias2 = b_out + Wout b_merge~
// ---------------------------------------------------------------------------
__global__ __launch_bounds__(256) void k_w2(const float* __restrict__ w_merge,
                                            const float* __restrict__ w_out) {
    __shared__ float wm[64 * 64];
    const int t = threadIdx.x;
    for (int i = t; i < 4096; i += 256) wm[i] = w_merge[i];
    __syncthreads();
    int idx = blockIdx.x * 256 + t;
    int c = idx >> 9, i = idx & 511;
    int h = i >> 6, d = i & 63;
    const float* wo = w_out + (size_t)c * INNER + h * 64;
    float s = 0.f;
#pragma unroll 8
    for (int dp = 0; dp < 64; dp++) s += wo[dp] * wm[dp * 64 + d];
    g_w2[idx] = s;
}

__global__ __launch_bounds__(256) void k_bias2(const float* __restrict__ w_out,
                                               const float* __restrict__ b_merge,
                                               const float* __restrict__ b_out) {
    int c = blockIdx.x * 8 + (threadIdx.x >> 5);
    int lane = threadIdx.x & 31;
    float s = 0.f;
    for (int i = lane; i < INNER; i += 32)
        s += w_out[(size_t)c * INNER + i] * b_merge[i & 63];
    for (int o = 16; o; o >>= 1) s += __shfl_xor_sync(~0u, s, o);
    if (lane == 0) g_b2[c] = b_out[c] + s;
}

__global__ __launch_bounds__(256) void k_copy(const float* __restrict__ src,
                                              float* __restrict__ dst, int n4) {
    int i = blockIdx.x * blockDim.x + threadIdx.x;
    if (i < n4) ((float4*)dst)[i] = ((const float4*)src)[i];
}

extern "C" void kernel_launch(void* const* d_in, const int* in_sizes, int n_in,
                              void* d_out, int out_size) {
    const float* x       = (const float*)d_in[0];
    const float* lidar   = (const float*)d_in[1];
    const float* w_qkv   = (const float*)d_in[2];
    const float* w_merge = (const float*)d_in[3];
    const float* b_merge = (const float*)d_in[4];
    const float* w_out   = (const float*)d_in[5];
    const float* b_out   = (const float*)d_in[6];
    const float* conv_w  = (const float*)d_in[7];
    float* out = (float*)d_out;

    const int flashSmem = (24576 + 5 * 64 + 256) * 4;   // ~98.3 KB
    cudaFuncSetAttribute(k_flash2, cudaFuncAttributeMaxDynamicSharedMemorySize,
                         flashSmem);

    // launch order keeps flash 4th (ncu captures launch #4)
    k_qkv<<<dim3(12, 64), 256>>>(x, w_qkv);
    k_lstats<<<dim3(8, G), 256>>>(lidar);
    k_w2<<<1024, 256>>>(w_merge, w_out);
    k_flash2<<<dim3(16, G), 256, flashSmem>>>(lidar, conv_w);
    k_bias2<<<64, 256>>>(w_out, b_merge, b_out);
    k_out<<<dim3(4, 64), 256>>>(out);

    const int outElems = B_ * N_ * DIM;
    if (out_size >= 2 * outElems)
        k_copy<<<(outElems / 4 + 255) / 256, 256>>>(lidar, out + outElems,
                                                    outElems / 4);
}

// round 10
// speedup vs baseline: 1.0804x; 1.0804x over previous
#include <cuda_runtime.h>
#include <cstdint>

namespace {
constexpr int B_ = 8, N_ = 1024, DIM = 512, H_ = 8, DH = 64, INNER = 512, G = 64;
constexpr float SCALE = 0.125f;
constexpr float LOG2E = 1.4426950408889634f;
}

// Scratch (device globals — allocation-free rule)
__device__ float g_q[(size_t)G * N_ * DH];
__device__ float g_k[(size_t)G * N_ * DH];
__device__ float g_v[(size_t)G * N_ * DH];
__device__ float g_y[(size_t)B_ * N_ * INNER];
__device__ float g_ml[G * N_];   // log2-domain row max of lidar logits
__device__ float g_isl[G * N_];  // 1 / sum exp2
__device__ float g_w2[DIM * INNER];
__device__ float g_b2[DIM];

// ---------------------------------------------------------------------------
// helpers
// ---------------------------------------------------------------------------
__device__ __forceinline__ float cvt_tf32f(float x) {
    unsigned r;
    asm("cvt.rna.tf32.f32 %0, %1;" : "=r"(r) : "f"(x));
    return __uint_as_float(r);
}
__device__ __forceinline__ float ex2f(float x) {
    float y;
    asm("ex2.approx.f32 %0, %1;" : "=f"(y) : "f"(x));
    return y;
}

__device__ __forceinline__ void mma8(float* d, const unsigned* a, const unsigned* b) {
    asm("mma.sync.aligned.m16n8k8.row.col.f32.tf32.tf32.f32 "
        "{%0,%1,%2,%3}, {%4,%5,%6,%7}, {%8,%9}, {%0,%1,%2,%3};"
        : "+f"(d[0]), "+f"(d[1]), "+f"(d[2]), "+f"(d[3])
        : "r"(a[0]), "r"(a[1]), "r"(a[2]), "r"(a[3]), "r"(b[0]), "r"(b[1]));
}

// Row swizzle: ((r&3)<<1) ^ (r&4). Even -> float2 pairing preserved; spreads
// rows r and r+4 to different banks (strides 40/72/136 == 8 mod 32).
__device__ __forceinline__ int swz(int r) { return ((r & 3) << 1) ^ (r & 4); }

// Permuted tile mma: pos(c) = 2*(c&3) + ((c&4)>>2), XOR swz(row).
template <int MT, int NT, int WARPS_N, int ASTR, int BSTR>
__device__ __forceinline__ void mma_slab_p(const float* As, const float* Bs,
                                           int warp, int g8, int t4,
                                           float (&acc)[MT][NT][4]) {
    const int wm = warp / WARPS_N, wn = warp % WARPS_N;
    const int po = (2 * t4) ^ swz(g8);
#pragma unroll
    for (int ks = 0; ks < 4; ks++) {
        const int off = ks * 8 + po;
        unsigned af[MT][4], bf[NT][2];
#pragma unroll
        for (int mt = 0; mt < MT; mt++) {
            int r = wm * (MT * 16) + mt * 16 + g8;
            float2 lo = *(const float2*)&As[r * ASTR + off];
            float2 hi = *(const float2*)&As[(r + 8) * ASTR + off];
            af[mt][0] = __float_as_uint(lo.x);
            af[mt][1] = __float_as_uint(hi.x);
            af[mt][2] = __float_as_uint(lo.y);
            af[mt][3] = __float_as_uint(hi.y);
        }
#pragma unroll
        for (int nt = 0; nt < NT; nt++) {
            int n = wn * (NT * 8) + nt * 8 + g8;
            float2 bv = *(const float2*)&Bs[n * BSTR + off];
            bf[nt][0] = __float_as_uint(bv.x);
            bf[nt][1] = __float_as_uint(bv.y);
        }
#pragma unroll
        for (int mt = 0; mt < MT; mt++)
#pragma unroll
            for (int nt = 0; nt < NT; nt++)
                mma8(acc[mt][nt], af[mt], bf[nt]);
    }
}

// PV: A = Ps (permuted, stride 136), B = Vs (k-major, stride 72). K=32 per call.
__device__ __forceinline__ void mma_pv(const float* Ps_, const float* Vs_,
                                       int warp, int g8, int t4,
                                       float (&acc)[2][4][4]) {
    const int wm2 = warp >> 1, wn2 = warp & 1;
    const int po = (2 * t4) ^ swz(g8);
#pragma unroll
    for (int ks = 0; ks < 4; ks++) {
        const int off = ks * 8 + po;
        const int c = ks * 8 + t4;
        unsigned af[2][4], bf[4][2];
#pragma unroll
        for (int mt = 0; mt < 2; mt++) {
            int r = wm2 * 32 + mt * 16 + g8;
            float2 lo = *(const float2*)&Ps_[r * 136 + off];
            float2 hi = *(const float2*)&Ps_[(r + 8) * 136 + off];
            af[mt][0] = __float_as_uint(lo.x);
            af[mt][1] = __float_as_uint(hi.x);
            af[mt][2] = __float_as_uint(lo.y);
            af[mt][3] = __float_as_uint(hi.y);
        }
#pragma unroll
        for (int nt = 0; nt < 4; nt++) {
            int n = wn2 * 32 + nt * 8 + g8;
            bf[nt][0] = __float_as_uint(Vs_[c * 72 + n]);
            bf[nt][1] = __float_as_uint(Vs_[(c + 4) * 72 + n]);
        }
#pragma unroll
        for (int mt = 0; mt < 2; mt++)
#pragma unroll
            for (int nt = 0; nt < 4; nt++)
                mma8(acc[mt][nt], af[mt], bf[nt]);
    }
}

struct R4T { float4 a[4]; };
__device__ __forceinline__ void ldg4(R4T& r, const float* g, int ld) {
    const int t = threadIdx.x;
    const int rr = t >> 3, c4 = (t & 7) * 4;
#pragma unroll
    for (int p = 0; p < 4; p++)
        r.a[p] = *(const float4*)(g + (size_t)(rr + p * 32) * ld + c4);
}
template <int STR>
__device__ __forceinline__ void sts4p(float* S, const R4T& r, float scale) {
    const int t = threadIdx.x;
    const int rr = t >> 3, c4 = (t & 7) * 4;
    const int start = (c4 & 24) + ((c4 & 4) ? 1 : 0);
#pragma unroll
    for (int p = 0; p < 4; p++) {
        int row = rr + p * 32;
        int sw = swz(row);
        float4 v = r.a[p];
        float* rp = S + row * STR;
        rp[(start + 0) ^ sw] = cvt_tf32f(v.x * scale);
        rp[(start + 2) ^ sw] = cvt_tf32f(v.y * scale);
        rp[(start + 4) ^ sw] = cvt_tf32f(v.z * scale);
        rp[(start + 6) ^ sw] = cvt_tf32f(v.w * scale);
    }
}

// ---------------------------------------------------------------------------
// K1: qkv = x @ w_qkv^T  -> head-major q/k/v  (double-buffered HMMA)
// ---------------------------------------------------------------------------
__global__ __launch_bounds__(256) void k_qkv(const float* __restrict__ x,
                                             const float* __restrict__ w) {
    __shared__ float As[2][128 * 40], Bs[2][128 * 40];
    const int t = threadIdx.x, warp = t >> 5, lane = t & 31;
    const int g8 = lane >> 2, t4 = lane & 3;
    const int n0 = blockIdx.x * 128, m0 = blockIdx.y * 128;
    float acc[4][4][4] = {};
    R4T ra, rb;
    ldg4(ra, x + (size_t)m0 * DIM, DIM);
    ldg4(rb, w + (size_t)n0 * DIM, DIM);
    sts4p<40>(As[0], ra, 1.f);
    sts4p<40>(Bs[0], rb, 1.f);
    __syncthreads();
    int cur = 0;
    for (int k0 = 32; k0 < DIM; k0 += 32) {
        ldg4(ra, x + (size_t)m0 * DIM + k0, DIM);
        ldg4(rb, w + (size_t)n0 * DIM + k0, DIM);
        mma_slab_p<4, 4, 4, 40, 40>(As[cur], Bs[cur], warp, g8, t4, acc);
        sts4p<40>(As[cur ^ 1], ra, 1.f);
        sts4p<40>(Bs[cur ^ 1], rb, 1.f);
        __syncthreads();
        cur ^= 1;
    }
    mma_slab_p<4, 4, 4, 40, 40>(As[cur], Bs[cur], warp, g8, t4, acc);
    const int wm = warp >> 2, wn = warp & 3;
#pragma unroll
    for (int mt = 0; mt < 4; mt++)
#pragma unroll
        for (int nt = 0; nt < 4; nt++) {
            int col = n0 + wn * 32 + nt * 8 + 2 * t4;
            int part = col >> 9, h = (col >> 6) & 7, d = col & 63;
            float* dst = part == 0 ? g_q : (part == 1 ? g_k : g_v);
#pragma unroll
            for (int half = 0; half < 2; half++) {
                int row = m0 + wm * 64 + mt * 16 + g8 + half * 8;
                int b = row >> 10, n = row & 1023;
                float2 val = half ? make_float2(acc[mt][nt][2], acc[mt][nt][3])
                                  : make_float2(acc[mt][nt][0], acc[mt][nt][1]);
                *(float2*)&dst[((size_t)((b * 8 + h) * 1024 + n)) * 64 + d] = val;
            }
        }
}

// ---------------------------------------------------------------------------
// K2: lidar softmax row stats in log2 domain.
// ---------------------------------------------------------------------------
__global__ __launch_bounds__(256) void k_lstats(const float* __restrict__ lidar) {
    __shared__ float Ali[2][128 * 40];
    __shared__ float Bs[2][128 * 40];
    __shared__ float red[4][128], bcast[128], mrun[128], srun[128];
    const int t = threadIdx.x, warp = t >> 5, lane = t & 31;
    const int g8 = lane >> 2, t4 = lane & 3;
    const int gidx = blockIdx.y, b = gidx >> 3, h = gidx & 7;
    const int i0 = blockIdx.x * 128;
    const float* base = lidar + (size_t)b * N_ * INNER + h * 64;
    const int wm = warp >> 2, wn = warp & 3;
    {
        R4T r0;
        ldg4(r0, base + (size_t)i0 * INNER, INNER);
        sts4p<40>(Ali[0], r0, SCALE * LOG2E);
        ldg4(r0, base + (size_t)i0 * INNER + 32, INNER);
        sts4p<40>(Ali[1], r0, SCALE * LOG2E);
    }
    if (t < 128) { mrun[t] = -1e30f; srun[t] = 0.f; }
    R4T rb;
    ldg4(rb, base, INNER);
    sts4p<40>(Bs[0], rb, 1.f);
    __syncthreads();
    int cur = 0;
    float acc[4][4][4];
    for (int idx = 0; idx < 16; idx++) {
        const int ks = idx & 1;
        if (ks == 0) {
#pragma unroll
            for (int a = 0; a < 4; a++)
#pragma unroll
                for (int c = 0; c < 4; c++)
#pragma unroll
                    for (int e = 0; e < 4; e++) acc[a][c][e] = 0.f;
        }
        if (idx < 15) {
            int nxt = idx + 1;
            ldg4(rb, base + (size_t)((nxt >> 1) * 128) * INNER + (nxt & 1) * 32,
                 INNER);
        }
        mma_slab_p<4, 4, 4, 40, 40>(Ali[ks], Bs[cur], warp, g8, t4, acc);
        if (idx < 15) sts4p<40>(Bs[cur ^ 1], rb, 1.f);
        __syncthreads();
        cur ^= 1;
        if (ks == 1) {
            float vm[4][2];
#pragma unroll
            for (int mt = 0; mt < 4; mt++) {
                float a0 = -1e30f, a1 = -1e30f;
#pragma unroll
                for (int nt = 0; nt < 4; nt++) {
                    a0 = fmaxf(a0, fmaxf(acc[mt][nt][0], acc[mt][nt][1]));
                    a1 = fmaxf(a1, fmaxf(acc[mt][nt][2], acc[mt][nt][3]));
                }
#pragma unroll
                for (int off = 1; off <= 2; off <<= 1) {
                    a0 = fmaxf(a0, __shfl_xor_sync(~0u, a0, off));
                    a1 = fmaxf(a1, __shfl_xor_sync(~0u, a1, off));
                }
                vm[mt][0] = a0; vm[mt][1] = a1;
            }
            if (t4 == 0)
#pragma unroll
                for (int mt = 0; mt < 4; mt++) {
                    red[wn][wm * 64 + mt * 16 + g8] = vm[mt][0];
                    red[wn][wm * 64 + mt * 16 + g8 + 8] = vm[mt][1];
                }
            __syncthreads();
            if (t < 128) {
                float tm = fmaxf(fmaxf(red[0][t], red[1][t]),
                                 fmaxf(red[2][t], red[3][t]));
                bcast[t] = fmaxf(mrun[t], tm);
            }
            __syncthreads();
            float vs[4][2];
#pragma unroll
            for (int mt = 0; mt < 4; mt++) {
                int r = wm * 64 + mt * 16 + g8;
                float mn0 = bcast[r], mn1 = bcast[r + 8];
                float s0 = 0.f, s1 = 0.f;
#pragma unroll
                for (int nt = 0; nt < 4; nt++) {
                    s0 += ex2f(acc[mt][nt][0] - mn0) + ex2f(acc[mt][nt][1] - mn0);
                    s1 += ex2f(acc[mt][nt][2] - mn1) + ex2f(acc[mt][nt][3] - mn1);
                }
#pragma unroll
                for (int off = 1; off <= 2; off <<= 1) {
                    s0 += __shfl_xor_sync(~0u, s0, off);
                    s1 += __shfl_xor_sync(~0u, s1, off);
                }
                vs[mt][0] = s0; vs[mt][1] = s1;
            }
            __syncthreads();
            if (t4 == 0)
#pragma unroll
                for (int mt = 0; mt < 4; mt++) {
                    red[wn][wm * 64 + mt * 16 + g8] = vs[mt][0];
                    red[wn][wm * 64 + mt * 16 + g8 + 8] = vs[mt][1];
                }
            __syncthreads();
            if (t < 128) {
                float ts = red[0][t] + red[1][t] + red[2][t] + red[3][t];
                float mn = bcast[t];
                srun[t] = srun[t] * ex2f(mrun[t] - mn) + ts;
                mrun[t] = mn;
            }
            __syncthreads();
        }
    }
    if (t < 128) {
        g_ml[gidx * N_ + i0 + t] = mrun[t];
        g_isl[gidx * N_ + i0 + t] = 1.0f / srun[t];
    }
}

// ---------------------------------------------------------------------------
// K3 (flash): BM=128, resident i-tiles, log2-domain softmax.
// ---------------------------------------------------------------------------
__global__ __launch_bounds__(256, 1) void k_flash(const float* __restrict__ lidar,
                                                  const float* __restrict__ conv_w) {
    extern __shared__ float sm[];
    float* AliL0 = sm;
    float* AliL1 = sm + 5120;
    float* AliQ0 = sm + 10240;
    float* AliQ1 = sm + 15360;
    float* Bs    = sm + 20480;            // 128*40
    float* Vs    = sm + 25600;            // 128*72
    float* Ps    = sm + 34816;            // 128*136
    float* mls   = sm + 52224;
    float* isls  = mls + 128;
    float* m_s   = isls + 128;
    float* l_s   = m_s + 128;
    float* al_s  = l_s + 128;
    float* red   = al_s + 128;            // 4*128

    const int t = threadIdx.x, warp = t >> 5, lane = t & 31;
    const int g8 = lane >> 2, t4 = lane & 3;
    const int gidx = blockIdx.y, i0 = blockIdx.x * 128;
    const int b = gidx >> 3, h = gidx & 7;
    const float c0s = conv_w[0] * SCALE * LOG2E;
    const float c1L = conv_w[1] * LOG2E;
    const int wm = warp >> 2, wn = warp & 3;
    const int wm2 = warp >> 1, wn2 = warp & 1;

    if (t < 128) {
        mls[t] = g_ml[gidx * N_ + i0 + t];
        isls[t] = g_isl[gidx * N_ + i0 + t];
        m_s[t] = -1e30f;
        l_s[t] = 0.f;
    }
    const float* lbase = lidar + (size_t)b * N_ * INNER + h * 64;
    const float* qb = g_q + (size_t)gidx * N_ * DH;
    const float* kb = g_k + (size_t)gidx * N_ * DH;
    const float* vb = g_v + (size_t)gidx * N_ * DH;

    R4T rb;
    ldg4(rb, lbase + (size_t)i0 * INNER, INNER);      sts4p<40>(AliL0, rb, SCALE * LOG2E);
    ldg4(rb, lbase + (size_t)i0 * INNER + 32, INNER); sts4p<40>(AliL1, rb, SCALE * LOG2E);
    ldg4(rb, qb + (size_t)i0 * DH, DH);               sts4p<40>(AliQ0, rb, c0s);
    ldg4(rb, qb + (size_t)i0 * DH + 32, DH);          sts4p<40>(AliQ1, rb, c0s);
    ldg4(rb, lbase, INNER);
    __syncthreads();

    float acc_o[2][4][4] = {};

    for (int j0 = 0; j0 < N_; j0 += 128) {
        float acc[4][4][4] = {};
        sts4p<40>(Bs, rb, 1.f);
        ldg4(rb, lbase + (size_t)j0 * INNER + 32, INNER);
        __syncthreads();
        mma_slab_p<4, 4, 4, 40, 40>(AliL0, Bs, warp, g8, t4, acc);
        __syncthreads();
        sts4p<40>(Bs, rb, 1.f);
        ldg4(rb, kb + (size_t)j0 * DH, DH);
        __syncthreads();
        mma_slab_p<4, 4, 4, 40, 40>(AliL1, Bs, warp, g8, t4, acc);
#pragma unroll
        for (int mt = 0; mt < 4; mt++) {
            int r = wm * 64 + mt * 16 + g8;
            float m0v = mls[r], i0v = isls[r] * c1L;
            float m1v = mls[r + 8], i1v = isls[r + 8] * c1L;
#pragma unroll
            for (int nt = 0; nt < 4; nt++) {
                acc[mt][nt][0] = i0v * ex2f(acc[mt][nt][0] - m0v);
                acc[mt][nt][1] = i0v * ex2f(acc[mt][nt][1] - m0v);
                acc[mt][nt][2] = i1v * ex2f(acc[mt][nt][2] - m1v);
                acc[mt][nt][3] = i1v * ex2f(acc[mt][nt][3] - m1v);
            }
        }
        __syncthreads();
        sts4p<40>(Bs, rb, 1.f);
        ldg4(rb, kb + (size_t)j0 * DH + 32, DH);
        __syncthreads();
        mma_slab_p<4, 4, 4, 40, 40>(AliQ0, Bs, warp, g8, t4, acc);
        __syncthreads();
        sts4p<40>(Bs, rb, 1.f);
        {
            const float* nxt = (j0 + 128 < N_) ? lbase + (size_t)(j0 + 128) * INNER
                                               : lbase;
            ldg4(rb, nxt, INNER);
        }
        __syncthreads();
        mma_slab_p<4, 4, 4, 40, 40>(AliQ1, Bs, warp, g8, t4, acc);
        float vm[4][2];
#pragma unroll
        for (int mt = 0; mt < 4; mt++) {
            float a0 = -1e30f, a1 = -1e30f;
#pragma unroll
            for (int nt = 0; nt < 4; nt++) {
                a0 = fmaxf(a0, fmaxf(acc[mt][nt][0], acc[mt][nt][1]));
                a1 = fmaxf(a1, fmaxf(acc[mt][nt][2], acc[mt][nt][3]));
            }
#pragma unroll
            for (int off = 1; off <= 2; off <<= 1) {
                a0 = fmaxf(a0, __shfl_xor_sync(~0u, a0, off));
                a1 = fmaxf(a1, __shfl_xor_sync(~0u, a1, off));
            }
            vm[mt][0] = a0; vm[mt][1] = a1;
        }
        if (t4 == 0)
#pragma unroll
            for (int mt = 0; mt < 4; mt++) {
                red[wn * 128 + wm * 64 + mt * 16 + g8] = vm[mt][0];
                red[wn * 128 + wm * 64 + mt * 16 + g8 + 8] = vm[mt][1];
            }
        __syncthreads();
        if (t < 128) {
            float tm = fmaxf(fmaxf(red[t], red[128 + t]),
                             fmaxf(red[256 + t], red[384 + t]));
            float mo = m_s[t];
            float mn = fmaxf(mo, tm);
            al_s[t] = ex2f(mo - mn);
            m_s[t] = mn;
        }
        __syncthreads();
        float vs[4][2];
        const int swp = swz(g8);
        const int pbase = ((2 * t4) & 3) * 2 + ((t4 & 2) ? 1 : 0);
#pragma unroll
        for (int mt = 0; mt < 4; mt++) {
            int r = wm * 64 + mt * 16 + g8;
            float mn0 = m_s[r], mn1 = m_s[r + 8];
            float s0 = 0.f, s1 = 0.f;
#pragma unroll
            for (int nt = 0; nt < 4; nt++) {
                float p0 = ex2f(acc[mt][nt][0] - mn0);
                float p1 = ex2f(acc[mt][nt][1] - mn0);
                float p2 = ex2f(acc[mt][nt][2] - mn1);
                float p3 = ex2f(acc[mt][nt][3] - mn1);
                s0 += p0 + p1; s1 += p2 + p3;
                int gp = wn * 32 + nt * 8;
                float* rowA = Ps + r * 136 + gp;
                float* rowB = Ps + (r + 8) * 136 + gp;
                rowA[(pbase + 0) ^ swp] = cvt_tf32f(p0);
                rowA[(pbase + 2) ^ swp] = cvt_tf32f(p1);
                rowB[(pbase + 0) ^ swp] = cvt_tf32f(p2);
                rowB[(pbase + 2) ^ swp] = cvt_tf32f(p3);
            }
#pragma unroll
            for (int off = 1; off <= 2; off <<= 1) {
                s0 += __shfl_xor_sync(~0u, s0, off);
                s1 += __shfl_xor_sync(~0u, s1, off);
            }
            vs[mt][0] = s0; vs[mt][1] = s1;
        }
        if (t4 == 0)
#pragma unroll
            for (int mt = 0; mt < 4; mt++) {
                red[wn * 128 + wm * 64 + mt * 16 + g8] = vs[mt][0];
                red[wn * 128 + wm * 64 + mt * 16 + g8 + 8] = vs[mt][1];
            }
        {
            int j = t >> 2, d16 = (t & 3) * 16;
#pragma unroll
            for (int p = 0; p < 2; p++) {
                int jj = j + p * 64;
                const float* src = vb + (size_t)(j0 + jj) * DH + d16;
#pragma unroll
                for (int q = 0; q < 4; q++) {
                    float4 v = *(const float4*)(src + q * 4);
                    float4 o;
                    o.x = cvt_tf32f(v.x); o.y = cvt_tf32f(v.y);
                    o.z = cvt_tf32f(v.z); o.w = cvt_tf32f(v.w);
                    *(float4*)(Vs + jj * 72 + d16 + q * 4) = o;
                }
            }
        }
        __syncthreads();
        if (t < 128)
            l_s[t] = l_s[t] * al_s[t] +
                     (red[t] + red[128 + t] + red[256 + t] + red[384 + t]);
#pragma unroll
        for (int mt = 0; mt < 2; mt++) {
            int r = wm2 * 32 + mt * 16 + g8;
            float a0 = al_s[r], a1 = al_s[r + 8];
#pragma unroll
            for (int nt = 0; nt < 4; nt++) {
                acc_o[mt][nt][0] *= a0; acc_o[mt][nt][1] *= a0;
                acc_o[mt][nt][2] *= a1; acc_o[mt][nt][3] *= a1;
            }
        }
#pragma unroll
        for (int slab = 0; slab < 4; slab++)
            mma_pv(Ps + slab * 32, Vs + (size_t)slab * 32 * 72,
                   warp, g8, t4, acc_o);
        __syncthreads();
    }
    float* yb = g_y + (size_t)b * N_ * INNER + h * 64;
#pragma unroll
    for (int mt = 0; mt < 2; mt++) {
        int r = wm2 * 32 + mt * 16 + g8;
        float inv0 = 1.0f / l_s[r], inv1 = 1.0f / l_s[r + 8];
#pragma unroll
        for (int nt = 0; nt < 4; nt++) {
            int d = wn2 * 32 + nt * 8 + 2 * t4;
            int n = i0 + r;
            *(float2*)&yb[(size_t)n * INNER + d] =
                make_float2(acc_o[mt][nt][0] * inv0, acc_o[mt][nt][1] * inv0);
            *(float2*)&yb[(size_t)(n + 8) * INNER + d] =
                make_float2(acc_o[mt][nt][2] * inv1, acc_o[mt][nt][3] * inv1);
        }
    }
}

// ---------------------------------------------------------------------------
// K4: out = y @ W2^T + bias2  (double-buffered HMMA)
// ---------------------------------------------------------------------------
__global__ __launch_bounds__(256) void k_out(float* __restrict__ out) {
    __shared__ float As[2][128 * 40], Bs[2][128 * 40];
    const int t = threadIdx.x, warp = t >> 5, lane = t & 31;
    const int g8 = lane >> 2, t4 = lane & 3;
    const int n0 = blockIdx.x * 128, m0 = blockIdx.y * 128;
    float acc[4][4][4] = {};
    R4T ra, rb;
    ldg4(ra, g_y + (size_t)m0 * INNER, INNER);
    ldg4(rb, g_w2 + (size_t)n0 * INNER, INNER);
    sts4p<40>(As[0], ra, 1.f);
    sts4p<40>(Bs[0], rb, 1.f);
    __syncthreads();
    int cur = 0;
    for (int k0 = 32; k0 < INNER; k0 += 32) {
        ldg4(ra, g_y + (size_t)m0 * INNER + k0, INNER);
        ldg4(rb, g_w2 + (size_t)n0 * INNER + k0, INNER);
        mma_slab_p<4, 4, 4, 40, 40>(As[cur], Bs[cur], warp, g8, t4, acc);
        sts4p<40>(As[cur ^ 1], ra, 1.f);
        sts4p<40>(Bs[cur ^ 1], rb, 1.f);
        __syncthreads();
        cur ^= 1;
    }
    mma_slab_p<4, 4, 4, 40, 40>(As[cur], Bs[cur], warp, g8, t4, acc);
    const int wm = warp >> 2, wn = warp & 3;
#pragma unroll
    for (int mt = 0; mt < 4; mt++)
#pragma unroll
        for (int nt = 0; nt < 4; nt++) {
            int col = n0 + wn * 32 + nt * 8 + 2 * t4;
            float b0 = g_b2[col], b1 = g_b2[col + 1];
            int r = m0 + wm * 64 + mt * 16 + g8;
            *(float2*)&out[(size_t)r * DIM + col] =
                make_float2(acc[mt][nt][0] + b0, acc[mt][nt][1] + b1);
            *(float2*)&out[(size_t)(r + 8) * DIM + col] =
                make_float2(acc[mt][nt][2] + b0, acc[mt][nt][3] + b1);
        }
}

// ---------------------------------------------------------------------------
// Precompute: W2 = Wout(.,h-block) @ Wm ; bias2 = b_out + Wout b_merge~
// ---------------------------------------------------------------------------
__global__ __launch_bounds__(256) void k_w2(const float* __restrict__ w_merge,
                                            const float* __restrict__ w_out) {
    __shared__ float wm[64 * 64];
    const int t = threadIdx.x;
    for (int i = t; i < 4096; i += 256) wm[i] = w_merge[i];
    __syncthreads();
    int idx = blockIdx.x * 256 + t;
    int c = idx >> 9, i = idx & 511;
    int h = i >> 6, d = i & 63;
    const float* wo = w_out + (size_t)c * INNER + h * 64;
    float s = 0.f;
#pragma unroll 8
    for (int dp = 0; dp < 64; dp++) s += wo[dp] * wm[dp * 64 + d];
    g_w2[idx] = s;
}

__global__ __launch_bounds__(256) void k_bias2(const float* __restrict__ w_out,
                                               const float* __restrict__ b_merge,
                                               const float* __restrict__ b_out) {
    int c = blockIdx.x * 8 + (threadIdx.x >> 5);
    int lane = threadIdx.x & 31;
    float s = 0.f;
    for (int i = lane; i < INNER; i += 32)
        s += w_out[(size_t)c * INNER + i] * b_merge[i & 63];
    for (int o = 16; o; o >>= 1) s += __shfl_xor_sync(~0u, s, o);
    if (lane == 0) g_b2[c] = b_out[c] + s;
}

__global__ __launch_bounds__(256) void k_copy(const float* __restrict__ src,
                                              float* __restrict__ dst, int n4) {
    int i = blockIdx.x * blockDim.x + threadIdx.x;
    if (i < n4) ((float4*)dst)[i] = ((const float4*)src)[i];
}

extern "C" void kernel_launch(void* const* d_in, const int* in_sizes, int n_in,
                              void* d_out, int out_size) {
    const float* x       = (const float*)d_in[0];
    const float* lidar   = (const float*)d_in[1];
    const float* w_qkv   = (const float*)d_in[2];
    const float* w_merge = (const float*)d_in[3];
    const float* b_merge = (const float*)d_in[4];
    const float* w_out   = (const float*)d_in[5];
    const float* b_out   = (const float*)d_in[6];
    const float* conv_w  = (const float*)d_in[7];
    float* out = (float*)d_out;

    const int flashSmem = (52224 + 5 * 128 + 512) * 4;   // 213.5 KB
    cudaFuncSetAttribute(k_flash, cudaFuncAttributeMaxDynamicSharedMemorySize,
                         flashSmem);

    // launch order keeps k_flash 4th (ncu captures launch #4)
    k_qkv<<<dim3(12, 64), 256>>>(x, w_qkv);
    k_lstats<<<dim3(8, G), 256>>>(lidar);
    k_w2<<<1024, 256>>>(w_merge, w_out);
    k_flash<<<dim3(8, G), 256, flashSmem>>>(lidar, conv_w);
    k_bias2<<<64, 256>>>(w_out, b_merge, b_out);
    k_out<<<dim3(4, 64), 256>>>(out);

    const int outElems = B_ * N_ * DIM;
    if (out_size >= 2 * outElems)
        k_copy<<<(outElems / 4 + 255) / 256, 256>>>(lidar, out + outElems,
                                                    outElems / 4);
}

// round 11
// speedup vs baseline: 1.1143x; 1.0314x over previous
#include <cuda_runtime.h>
#include <cstdint>

namespace {
constexpr int B_ = 8, N_ = 1024, DIM = 512, H_ = 8, DH = 64, INNER = 512, G = 64;
constexpr float SCALE = 0.125f;
constexpr float LOG2E = 1.4426950408889634f;
}

// Scratch (device globals — allocation-free rule)
__device__ float g_q[(size_t)G * N_ * DH];
__device__ float g_k[(size_t)G * N_ * DH];
__device__ float g_v[(size_t)G * N_ * DH];
__device__ float g_y[(size_t)B_ * N_ * INNER];
__device__ float g_ml[G * N_];   // log2-domain row max of lidar logits
__device__ float g_isl[G * N_];  // 1 / sum exp2
__device__ float g_mi[G * N_];   // per-row upper bound of blended logit (log2)
__device__ float g_w2[DIM * INNER];
__device__ float g_b2[DIM];

// ---------------------------------------------------------------------------
// helpers
// ---------------------------------------------------------------------------
__device__ __forceinline__ float cvt_tf32f(float x) {
    unsigned r;
    asm("cvt.rna.tf32.f32 %0, %1;" : "=r"(r) : "f"(x));
    return __uint_as_float(r);
}
__device__ __forceinline__ float ex2f(float x) {
    float y;
    asm("ex2.approx.f32 %0, %1;" : "=f"(y) : "f"(x));
    return y;
}

__device__ __forceinline__ void mma8(float* d, const unsigned* a, const unsigned* b) {
    asm("mma.sync.aligned.m16n8k8.row.col.f32.tf32.tf32.f32 "
        "{%0,%1,%2,%3}, {%4,%5,%6,%7}, {%8,%9}, {%0,%1,%2,%3};"
        : "+f"(d[0]), "+f"(d[1]), "+f"(d[2]), "+f"(d[3])
        : "r"(a[0]), "r"(a[1]), "r"(a[2]), "r"(a[3]), "r"(b[0]), "r"(b[1]));
}

// Row swizzle: ((r&3)<<1) ^ (r&4).
__device__ __forceinline__ int swz(int r) { return ((r & 3) << 1) ^ (r & 4); }

// Permuted tile mma: pos(c) = 2*(c&3) + ((c&4)>>2), XOR swz(row).
template <int MT, int NT, int WARPS_N, int ASTR, int BSTR>
__device__ __forceinline__ void mma_slab_p(const float* As, const float* Bs,
                                           int warp, int g8, int t4,
                                           float (&acc)[MT][NT][4]) {
    const int wm = warp / WARPS_N, wn = warp % WARPS_N;
    const int po = (2 * t4) ^ swz(g8);
#pragma unroll
    for (int ks = 0; ks < 4; ks++) {
        const int off = ks * 8 + po;
        unsigned af[MT][4], bf[NT][2];
#pragma unroll
        for (int mt = 0; mt < MT; mt++) {
            int r = wm * (MT * 16) + mt * 16 + g8;
            float2 lo = *(const float2*)&As[r * ASTR + off];
            float2 hi = *(const float2*)&As[(r + 8) * ASTR + off];
            af[mt][0] = __float_as_uint(lo.x);
            af[mt][1] = __float_as_uint(hi.x);
            af[mt][2] = __float_as_uint(lo.y);
            af[mt][3] = __float_as_uint(hi.y);
        }
#pragma unroll
        for (int nt = 0; nt < NT; nt++) {
            int n = wn * (NT * 8) + nt * 8 + g8;
            float2 bv = *(const float2*)&Bs[n * BSTR + off];
            bf[nt][0] = __float_as_uint(bv.x);
            bf[nt][1] = __float_as_uint(bv.y);
        }
#pragma unroll
        for (int mt = 0; mt < MT; mt++)
#pragma unroll
            for (int nt = 0; nt < NT; nt++)
                mma8(acc[mt][nt], af[mt], bf[nt]);
    }
}

// PV: A = Ps (permuted, stride 136), B = Vs (k-major, stride 72). K=32 per call.
__device__ __forceinline__ void mma_pv(const float* Ps_, const float* Vs_,
                                       int warp, int g8, int t4,
                                       float (&acc)[2][4][4]) {
    const int wm2 = warp >> 1, wn2 = warp & 1;
    const int po = (2 * t4) ^ swz(g8);
#pragma unroll
    for (int ks = 0; ks < 4; ks++) {
        const int off = ks * 8 + po;
        const int c = ks * 8 + t4;
        unsigned af[2][4], bf[4][2];
#pragma unroll
        for (int mt = 0; mt < 2; mt++) {
            int r = wm2 * 32 + mt * 16 + g8;
            float2 lo = *(const float2*)&Ps_[r * 136 + off];
            float2 hi = *(const float2*)&Ps_[(r + 8) * 136 + off];
            af[mt][0] = __float_as_uint(lo.x);
            af[mt][1] = __float_as_uint(hi.x);
            af[mt][2] = __float_as_uint(lo.y);
            af[mt][3] = __float_as_uint(hi.y);
        }
#pragma unroll
        for (int nt = 0; nt < 4; nt++) {
            int n = wn2 * 32 + nt * 8 + g8;
            bf[nt][0] = __float_as_uint(Vs_[c * 72 + n]);
            bf[nt][1] = __float_as_uint(Vs_[(c + 4) * 72 + n]);
        }
#pragma unroll
        for (int mt = 0; mt < 2; mt++)
#pragma unroll
            for (int nt = 0; nt < 4; nt++)
                mma8(acc[mt][nt], af[mt], bf[nt]);
    }
}

struct R4T { float4 a[4]; };
__device__ __forceinline__ void ldg4(R4T& r, const float* g, int ld) {
    const int t = threadIdx.x;
    const int rr = t >> 3, c4 = (t & 7) * 4;
#pragma unroll
    for (int p = 0; p < 4; p++)
        r.a[p] = *(const float4*)(g + (size_t)(rr + p * 32) * ld + c4);
}
template <int STR>
__device__ __forceinline__ void sts4p(float* S, const R4T& r, float scale) {
    const int t = threadIdx.x;
    const int rr = t >> 3, c4 = (t & 7) * 4;
    const int start = (c4 & 24) + ((c4 & 4) ? 1 : 0);
#pragma unroll
    for (int p = 0; p < 4; p++) {
        int row = rr + p * 32;
        int sw = swz(row);
        float4 v = r.a[p];
        float* rp = S + row * STR;
        rp[(start + 0) ^ sw] = cvt_tf32f(v.x * scale);
        rp[(start + 2) ^ sw] = cvt_tf32f(v.y * scale);
        rp[(start + 4) ^ sw] = cvt_tf32f(v.z * scale);
        rp[(start + 6) ^ sw] = cvt_tf32f(v.w * scale);
    }
}

// ---------------------------------------------------------------------------
// K1: qkv = x @ w_qkv^T  -> head-major q/k/v  (double-buffered HMMA)
// ---------------------------------------------------------------------------
__global__ __launch_bounds__(256) void k_qkv(const float* __restrict__ x,
                                             const float* __restrict__ w) {
    __shared__ float As[2][128 * 40], Bs[2][128 * 40];
    const int t = threadIdx.x, warp = t >> 5, lane = t & 31;
    const int g8 = lane >> 2, t4 = lane & 3;
    const int n0 = blockIdx.x * 128, m0 = blockIdx.y * 128;
    float acc[4][4][4] = {};
    R4T ra, rb;
    ldg4(ra, x + (size_t)m0 * DIM, DIM);
    ldg4(rb, w + (size_t)n0 * DIM, DIM);
    sts4p<40>(As[0], ra, 1.f);
    sts4p<40>(Bs[0], rb, 1.f);
    __syncthreads();
    int cur = 0;
    for (int k0 = 32; k0 < DIM; k0 += 32) {
        ldg4(ra, x + (size_t)m0 * DIM + k0, DIM);
        ldg4(rb, w + (size_t)n0 * DIM + k0, DIM);
        mma_slab_p<4, 4, 4, 40, 40>(As[cur], Bs[cur], warp, g8, t4, acc);
        sts4p<40>(As[cur ^ 1], ra, 1.f);
        sts4p<40>(Bs[cur ^ 1], rb, 1.f);
        __syncthreads();
        cur ^= 1;
    }
    mma_slab_p<4, 4, 4, 40, 40>(As[cur], Bs[cur], warp, g8, t4, acc);
    const int wm = warp >> 2, wn = warp & 3;
#pragma unroll
    for (int mt = 0; mt < 4; mt++)
#pragma unroll
        for (int nt = 0; nt < 4; nt++) {
            int col = n0 + wn * 32 + nt * 8 + 2 * t4;
            int part = col >> 9, h = (col >> 6) & 7, d = col & 63;
            float* dst = part == 0 ? g_q : (part == 1 ? g_k : g_v);
#pragma unroll
            for (int half = 0; half < 2; half++) {
                int row = m0 + wm * 64 + mt * 16 + g8 + half * 8;
                int b = row >> 10, n = row & 1023;
                float2 val = half ? make_float2(acc[mt][nt][2], acc[mt][nt][3])
                                  : make_float2(acc[mt][nt][0], acc[mt][nt][1]);
                *(float2*)&dst[((size_t)((b * 8 + h) * 1024 + n)) * 64 + d] = val;
            }
        }
}

// ---------------------------------------------------------------------------
// K1b: per-row logit upper bound (log2 domain):
//   m_i = |c0*SCALE*log2e| * ||q_i|| * max_j||k_j||  +  max(c1*log2e, 0)
// ---------------------------------------------------------------------------
__global__ __launch_bounds__(256) void k_bound(const float* __restrict__ conv_w) {
    __shared__ float red[8];
    __shared__ float smax;
    const int g = blockIdx.x, t = threadIdx.x;
    const float* kb = g_k + (size_t)g * N_ * DH;
    float mx = 0.f;
    for (int j = t; j < N_; j += 256) {
        const float4* r4 = (const float4*)(kb + (size_t)j * DH);
        float s = 0.f;
#pragma unroll
        for (int q = 0; q < 16; q++) {
            float4 v = r4[q];
            s += v.x * v.x + v.y * v.y + v.z * v.z + v.w * v.w;
        }
        mx = fmaxf(mx, s);
    }
    for (int o = 16; o; o >>= 1) mx = fmaxf(mx, __shfl_xor_sync(~0u, mx, o));
    if ((t & 31) == 0) red[t >> 5] = mx;
    __syncthreads();
    if (t == 0) {
        float m = red[0];
#pragma unroll
        for (int w = 1; w < 8; w++) m = fmaxf(m, red[w]);
        smax = m;
    }
    __syncthreads();
    const float maxkk = smax;
    const float c0a = fabsf(conv_w[0]) * SCALE * LOG2E;
    const float c1L = conv_w[1] * LOG2E;
    const float* qb = g_q + (size_t)g * N_ * DH;
    for (int i = t; i < N_; i += 256) {
        const float4* r4 = (const float4*)(qb + (size_t)i * DH);
        float s = 0.f;
#pragma unroll
        for (int q = 0; q < 16; q++) {
            float4 v = r4[q];
            s += v.x * v.x + v.y * v.y + v.z * v.z + v.w * v.w;
        }
        g_mi[g * N_ + i] = c0a * sqrtf(s * maxkk) + fmaxf(c1L, 0.f);
    }
}

// ---------------------------------------------------------------------------
// K2: lidar softmax row stats in log2 domain (online, exact).
// ---------------------------------------------------------------------------
__global__ __launch_bounds__(256) void k_lstats(const float* __restrict__ lidar) {
    __shared__ float Ali[2][128 * 40];
    __shared__ float Bs[2][128 * 40];
    __shared__ float red[4][128], bcast[128], mrun[128], srun[128];
    const int t = threadIdx.x, warp = t >> 5, lane = t & 31;
    const int g8 = lane >> 2, t4 = lane & 3;
    const int gidx = blockIdx.y, b = gidx >> 3, h = gidx & 7;
    const int i0 = blockIdx.x * 128;
    const float* base = lidar + (size_t)b * N_ * INNER + h * 64;
    const int wm = warp >> 2, wn = warp & 3;
    {
        R4T r0;
        ldg4(r0, base + (size_t)i0 * INNER, INNER);
        sts4p<40>(Ali[0], r0, SCALE * LOG2E);
        ldg4(r0, base + (size_t)i0 * INNER + 32, INNER);
        sts4p<40>(Ali[1], r0, SCALE * LOG2E);
    }
    if (t < 128) { mrun[t] = -1e30f; srun[t] = 0.f; }
    R4T rb;
    ldg4(rb, base, INNER);
    sts4p<40>(Bs[0], rb, 1.f);
    __syncthreads();
    int cur = 0;
    float acc[4][4][4];
    for (int idx = 0; idx < 16; idx++) {
        const int ks = idx & 1;
        if (ks == 0) {
#pragma unroll
            for (int a = 0; a < 4; a++)
#pragma unroll
                for (int c = 0; c < 4; c++)
#pragma unroll
                    for (int e = 0; e < 4; e++) acc[a][c][e] = 0.f;
        }
        if (idx < 15) {
            int nxt = idx + 1;
            ldg4(rb, base + (size_t)((nxt >> 1) * 128) * INNER + (nxt & 1) * 32,
                 INNER);
        }
        mma_slab_p<4, 4, 4, 40, 40>(Ali[ks], Bs[cur], warp, g8, t4, acc);
        if (idx < 15) sts4p<40>(Bs[cur ^ 1], rb, 1.f);
        __syncthreads();
        cur ^= 1;
        if (ks == 1) {
            float vm[4][2];
#pragma unroll
            for (int mt = 0; mt < 4; mt++) {
                float a0 = -1e30f, a1 = -1e30f;
#pragma unroll
                for (int nt = 0; nt < 4; nt++) {
                    a0 = fmaxf(a0, fmaxf(acc[mt][nt][0], acc[mt][nt][1]));
                    a1 = fmaxf(a1, fmaxf(acc[mt][nt][2], acc[mt][nt][3]));
                }
#pragma unroll
                for (int off = 1; off <= 2; off <<= 1) {
                    a0 = fmaxf(a0, __shfl_xor_sync(~0u, a0, off));
                    a1 = fmaxf(a1, __shfl_xor_sync(~0u, a1, off));
                }
                vm[mt][0] = a0; vm[mt][1] = a1;
            }
            if (t4 == 0)
#pragma unroll
                for (int mt = 0; mt < 4; mt++) {
                    red[wn][wm * 64 + mt * 16 + g8] = vm[mt][0];
                    red[wn][wm * 64 + mt * 16 + g8 + 8] = vm[mt][1];
                }
            __syncthreads();
            if (t < 128) {
                float tm = fmaxf(fmaxf(red[0][t], red[1][t]),
                                 fmaxf(red[2][t], red[3][t]));
                bcast[t] = fmaxf(mrun[t], tm);
            }
            __syncthreads();
            float vs[4][2];
#pragma unroll
            for (int mt = 0; mt < 4; mt++) {
                int r = wm * 64 + mt * 16 + g8;
                float mn0 = bcast[r], mn1 = bcast[r + 8];
                float s0 = 0.f, s1 = 0.f;
#pragma unroll
                for (int nt = 0; nt < 4; nt++) {
                    s0 += ex2f(acc[mt][nt][0] - mn0) + ex2f(acc[mt][nt][1] - mn0);
                    s1 += ex2f(acc[mt][nt][2] - mn1) + ex2f(acc[mt][nt][3] - mn1);
                }
#pragma unroll
                for (int off = 1; off <= 2; off <<= 1) {
                    s0 += __shfl_xor_sync(~0u, s0, off);
                    s1 += __shfl_xor_sync(~0u, s1, off);
                }
                vs[mt][0] = s0; vs[mt][1] = s1;
            }
            __syncthreads();
            if (t4 == 0)
#pragma unroll
                for (int mt = 0; mt < 4; mt++) {
                    red[wn][wm * 64 + mt * 16 + g8] = vs[mt][0];
                    red[wn][wm * 64 + mt * 16 + g8 + 8] = vs[mt][1];
                }
            __syncthreads();
            if (t < 128) {
                float ts = red[0][t] + red[1][t] + red[2][t] + red[3][t];
                float mn = bcast[t];
                srun[t] = srun[t] * ex2f(mrun[t] - mn) + ts;
                mrun[t] = mn;
            }
            __syncthreads();
        }
    }
    if (t < 128) {
        g_ml[gidx * N_ + i0 + t] = mrun[t];
        g_isl[gidx * N_ + i0 + t] = 1.0f / srun[t];
    }
}

// ---------------------------------------------------------------------------
// K3 (flash): single-pass softmax with precomputed per-row bound.
// 6 barriers/iter, no reductions in the loop.
// ---------------------------------------------------------------------------
__global__ __launch_bounds__(256, 1) void k_flash(const float* __restrict__ lidar,
                                                  const float* __restrict__ conv_w) {
    extern __shared__ float sm[];
    float* AliL0 = sm;
    float* AliL1 = sm + 5120;
    float* AliQ0 = sm + 10240;
    float* AliQ1 = sm + 15360;
    float* Bs    = sm + 20480;            // 128*40 (slab-even B)
    float* Vs    = sm + 25600;            // 128*72 (slab-odd B, then V)
    float* Ps    = sm + 34816;            // 128*136
    float* mls   = sm + 52224;
    float* isls  = mls + 128;
    float* m_s   = isls + 128;            // fixed per-row bound
    float* l_s   = m_s + 128;             // final inverse row-sums
    float* red   = l_s + 256;             // 4*128

    const int t = threadIdx.x, warp = t >> 5, lane = t & 31;
    const int g8 = lane >> 2, t4 = lane & 3;
    const int gidx = blockIdx.y, i0 = blockIdx.x * 128;
    const int b = gidx >> 3, h = gidx & 7;
    const float c0s = conv_w[0] * SCALE * LOG2E;
    const float c1L = conv_w[1] * LOG2E;
    const int wm = warp >> 2, wn = warp & 3;
    const int wm2 = warp >> 1, wn2 = warp & 1;

    if (t < 128) {
        mls[t] = g_ml[gidx * N_ + i0 + t];
        isls[t] = g_isl[gidx * N_ + i0 + t];
        m_s[t] = g_mi[gidx * N_ + i0 + t];
    }
    const float* lbase = lidar + (size_t)b * N_ * INNER + h * 64;
    const float* qb = g_q + (size_t)gidx * N_ * DH;
    const float* kb = g_k + (size_t)gidx * N_ * DH;
    const float* vb = g_v + (size_t)gidx * N_ * DH;

    R4T ra, rb;
    ldg4(ra, lbase + (size_t)i0 * INNER, INNER);      sts4p<40>(AliL0, ra, SCALE * LOG2E);
    ldg4(ra, lbase + (size_t)i0 * INNER + 32, INNER); sts4p<40>(AliL1, ra, SCALE * LOG2E);
    ldg4(ra, qb + (size_t)i0 * DH, DH);               sts4p<40>(AliQ0, ra, c0s);
    ldg4(ra, qb + (size_t)i0 * DH + 32, DH);          sts4p<40>(AliQ1, ra, c0s);
    // prefetch first lidar j-tile
    ldg4(ra, lbase, INNER);
    ldg4(rb, lbase + 32, INNER);
    __syncthreads();

    float acc_o[2][4][4] = {};
    float lp[4][2] = {};                  // per-thread row sums (score layout)
    float4 vreg[8];

    const int vjr = t >> 2, vdc = (t & 3) * 16;

    for (int j0 = 0; j0 < N_; j0 += 128) {
        float acc[4][4][4] = {};
        // stage lidar j-tile slabs (Bs + Vs-as-B); prefetch K tiles
        sts4p<40>(Bs, ra, 1.f);
        sts4p<72>(Vs, rb, 1.f);
        ldg4(ra, kb + (size_t)j0 * DH, DH);
        ldg4(rb, kb + (size_t)j0 * DH + 32, DH);
        __syncthreads();                               // B
        mma_slab_p<4, 4, 4, 40, 40>(AliL0, Bs, warp, g8, t4, acc);
        mma_slab_p<4, 4, 4, 40, 72>(AliL1, Vs, warp, g8, t4, acc);
        // lidar softmax transform (fixed stats)
#pragma unroll
        for (int mt = 0; mt < 4; mt++) {
            int r = wm * 64 + mt * 16 + g8;
            float m0v = mls[r], i0v = isls[r] * c1L;
            float m1v = mls[r + 8], i1v = isls[r + 8] * c1L;
#pragma unroll
            for (int nt = 0; nt < 4; nt++) {
                acc[mt][nt][0] = i0v * ex2f(acc[mt][nt][0] - m0v);
                acc[mt][nt][1] = i0v * ex2f(acc[mt][nt][1] - m0v);
                acc[mt][nt][2] = i1v * ex2f(acc[mt][nt][2] - m1v);
                acc[mt][nt][3] = i1v * ex2f(acc[mt][nt][3] - m1v);
            }
        }
        __syncthreads();                               // C
        // stage K j-tile slabs; prefetch V tile into regs
        sts4p<40>(Bs, ra, 1.f);
        sts4p<72>(Vs, rb, 1.f);
        {
            const float* src = vb + (size_t)(j0 + vjr) * DH + vdc;
#pragma unroll
            for (int q = 0; q < 4; q++) vreg[q] = *(const float4*)(src + q * 4);
            src += (size_t)64 * DH;
#pragma unroll
            for (int q = 0; q < 4; q++) vreg[4 + q] = *(const float4*)(src + q * 4);
        }
        __syncthreads();                               // D
        mma_slab_p<4, 4, 4, 40, 40>(AliQ0, Bs, warp, g8, t4, acc);
        mma_slab_p<4, 4, 4, 40, 72>(AliQ1, Vs, warp, g8, t4, acc);
        // P = exp2(acc - m_bound) -> Ps; accumulate row sums in regs
        {
            const int swp = swz(g8);
            const int pbase = ((2 * t4) & 3) * 2 + ((t4 & 2) ? 1 : 0);
#pragma unroll
            for (int mt = 0; mt < 4; mt++) {
                int r = wm * 64 + mt * 16 + g8;
                float mn0 = m_s[r], mn1 = m_s[r + 8];
                float s0 = 0.f, s1 = 0.f;
#pragma unroll
                for (int nt = 0; nt < 4; nt++) {
                    float p0 = ex2f(acc[mt][nt][0] - mn0);
                    float p1 = ex2f(acc[mt][nt][1] - mn0);
                    float p2 = ex2f(acc[mt][nt][2] - mn1);
                    float p3 = ex2f(acc[mt][nt][3] - mn1);
                    s0 += p0 + p1; s1 += p2 + p3;
                    int gp = wn * 32 + nt * 8;
                    float* rowA = Ps + r * 136 + gp;
                    float* rowB = Ps + (r + 8) * 136 + gp;
                    rowA[(pbase + 0) ^ swp] = cvt_tf32f(p0);
                    rowA[(pbase + 2) ^ swp] = cvt_tf32f(p1);
                    rowB[(pbase + 0) ^ swp] = cvt_tf32f(p2);
                    rowB[(pbase + 2) ^ swp] = cvt_tf32f(p3);
                }
                lp[mt][0] += s0; lp[mt][1] += s1;
            }
        }
        __syncthreads();                               // E (Vs free)
        // V tile -> Vs (k-major, stride 72)
#pragma unroll
        for (int p = 0; p < 2; p++) {
            int jj = vjr + p * 64;
#pragma unroll
            for (int q = 0; q < 4; q++) {
                float4 v = vreg[p * 4 + q];
                float4 o;
                o.x = cvt_tf32f(v.x); o.y = cvt_tf32f(v.y);
                o.z = cvt_tf32f(v.z); o.w = cvt_tf32f(v.w);
                *(float4*)(Vs + jj * 72 + vdc + q * 4) = o;
            }
        }
        // prefetch next lidar j-tile (consumed next iter; regs idle during PV)
        {
            const float* nxt = lbase + (size_t)((j0 + 128) & (N_ - 1)) * INNER;
            ldg4(ra, nxt, INNER);
            ldg4(rb, nxt + 32, INNER);
        }
        __syncthreads();                               // F
        // O += P @ V
#pragma unroll
        for (int slab = 0; slab < 4; slab++)
            mma_pv(Ps + slab * 32, Vs + (size_t)slab * 32 * 72,
                   warp, g8, t4, acc_o);
        __syncthreads();                               // A (next iter)
    }
    // final row-sum reduction (once)
#pragma unroll
    for (int mt = 0; mt < 4; mt++) {
        float s0 = lp[mt][0], s1 = lp[mt][1];
#pragma unroll
        for (int off = 1; off <= 2; off <<= 1) {
            s0 += __shfl_xor_sync(~0u, s0, off);
            s1 += __shfl_xor_sync(~0u, s1, off);
        }
        if (t4 == 0) {
            red[wn * 128 + wm * 64 + mt * 16 + g8] = s0;
            red[wn * 128 + wm * 64 + mt * 16 + g8 + 8] = s1;
        }
    }
    __syncthreads();
    if (t < 128)
        l_s[t] = 1.0f / (red[t] + red[128 + t] + red[256 + t] + red[384 + t]);
    __syncthreads();
    float* yb = g_y + (size_t)b * N_ * INNER + h * 64;
#pragma unroll
    for (int mt = 0; mt < 2; mt++) {
        int r = wm2 * 32 + mt * 16 + g8;
        float inv0 = l_s[r], inv1 = l_s[r + 8];
#pragma unroll
        for (int nt = 0; nt < 4; nt++) {
            int d = wn2 * 32 + nt * 8 + 2 * t4;
            int n = i0 + r;
            *(float2*)&yb[(size_t)n * INNER + d] =
                make_float2(acc_o[mt][nt][0] * inv0, acc_o[mt][nt][1] * inv0);
            *(float2*)&yb[(size_t)(n + 8) * INNER + d] =
                make_float2(acc_o[mt][nt][2] * inv1, acc_o[mt][nt][3] * inv1);
        }
    }
}

// ---------------------------------------------------------------------------
// K4: out = y @ W2^T + bias2  (double-buffered HMMA)
// ---------------------------------------------------------------------------
__global__ __launch_bounds__(256) void k_out(float* __restrict__ out) {
    __shared__ float As[2][128 * 40], Bs[2][128 * 40];
    const int t = threadIdx.x, warp = t >> 5, lane = t & 31;
    const int g8 = lane >> 2, t4 = lane & 3;
    const int n0 = blockIdx.x * 128, m0 = blockIdx.y * 128;
    float acc[4][4][4] = {};
    R4T ra, rb;
    ldg4(ra, g_y + (size_t)m0 * INNER, INNER);
    ldg4(rb, g_w2 + (size_t)n0 * INNER, INNER);
    sts4p<40>(As[0], ra, 1.f);
    sts4p<40>(Bs[0], rb, 1.f);
    __syncthreads();
    int cur = 0;
    for (int k0 = 32; k0 < INNER; k0 += 32) {
        ldg4(ra, g_y + (size_t)m0 * INNER + k0, INNER);
        ldg4(rb, g_w2 + (size_t)n0 * INNER + k0, INNER);
        mma_slab_p<4, 4, 4, 40, 40>(As[cur], Bs[cur], warp, g8, t4, acc);
        sts4p<40>(As[cur ^ 1], ra, 1.f);
        sts4p<40>(Bs[cur ^ 1], rb, 1.f);
        __syncthreads();
        cur ^= 1;
    }
    mma_slab_p<4, 4, 4, 40, 40>(As[cur], Bs[cur], warp, g8, t4, acc);
    const int wm = warp >> 2, wn = warp & 3;
#pragma unroll
    for (int mt = 0; mt < 4; mt++)
#pragma unroll
        for (int nt = 0; nt < 4; nt++) {
            int col = n0 + wn * 32 + nt * 8 + 2 * t4;
            float b0 = g_b2[col], b1 = g_b2[col + 1];
            int r = m0 + wm * 64 + mt * 16 + g8;
            *(float2*)&out[(size_t)r * DIM + col] =
                make_float2(acc[mt][nt][0] + b0, acc[mt][nt][1] + b1);
            *(float2*)&out[(size_t)(r + 8) * DIM + col] =
                make_float2(acc[mt][nt][2] + b0, acc[mt][nt][3] + b1);
        }
}

// ---------------------------------------------------------------------------
// Precompute: W2 = Wout(.,h-block) @ Wm ; bias2 = b_out + Wout b_merge~
// ---------------------------------------------------------------------------
__global__ __launch_bounds__(256) void k_w2(const float* __restrict__ w_merge,
                                            const float* __restrict__ w_out) {
    __shared__ float wm[64 * 64];
    const int t = threadIdx.x;
    for (int i = t; i < 4096; i += 256) wm[i] = w_merge[i];
    __syncthreads();
    int idx = blockIdx.x * 256 + t;
    int c = idx >> 9, i = idx & 511;
    int h = i >> 6, d = i & 63;
    const float* wo = w_out + (size_t)c * INNER + h * 64;
    float s = 0.f;
#pragma unroll 8
    for (int dp = 0; dp < 64; dp++) s += wo[dp] * wm[dp * 64 + d];
    g_w2[idx] = s;
}

__global__ __launch_bounds__(256) void k_bias2(const float* __restrict__ w_out,
                                               const float* __restrict__ b_merge,
                                               const float* __restrict__ b_out) {
    int c = blockIdx.x * 8 + (threadIdx.x >> 5);
    int lane = threadIdx.x & 31;
    float s = 0.f;
    for (int i = lane; i < INNER; i += 32)
        s += w_out[(size_t)c * INNER + i] * b_merge[i & 63];
    for (int o = 16; o; o >>= 1) s += __shfl_xor_sync(~0u, s, o);
    if (lane == 0) g_b2[c] = b_out[c] + s;
}

__global__ __launch_bounds__(256) void k_copy(const float* __restrict__ src,
                                              float* __restrict__ dst, int n4) {
    int i = blockIdx.x * blockDim.x + threadIdx.x;
    if (i < n4) ((float4*)dst)[i] = ((const float4*)src)[i];
}

extern "C" void kernel_launch(void* const* d_in, const int* in_sizes, int n_in,
                              void* d_out, int out_size) {
    const float* x       = (const float*)d_in[0];
    const float* lidar   = (const float*)d_in[1];
    const float* w_qkv   = (const float*)d_in[2];
    const float* w_merge = (const float*)d_in[3];
    const float* b_merge = (const float*)d_in[4];
    const float* w_out   = (const float*)d_in[5];
    const float* b_out   = (const float*)d_in[6];
    const float* conv_w  = (const float*)d_in[7];
    float* out = (float*)d_out;

    const int flashSmem = (52224 + 4 * 128 + 512 + 256) * 4;   // ~214 KB
    cudaFuncSetAttribute(k_flash, cudaFuncAttributeMaxDynamicSharedMemorySize,
                         flashSmem);

    // launch order keeps k_flash 4th (ncu captures launch #4)
    k_qkv<<<dim3(12, 64), 256>>>(x, w_qkv);
    k_bound<<<G, 256>>>(conv_w);
    k_lstats<<<dim3(8, G), 256>>>(lidar);
    k_flash<<<dim3(8, G), 256, flashSmem>>>(lidar, conv_w);
    k_w2<<<1024, 256>>>(w_merge, w_out);
    k_bias2<<<64, 256>>>(w_out, b_merge, b_out);
    k_out<<<dim3(4, 64), 256>>>(out);

    const int outElems = B_ * N_ * DIM;
    if (out_size >= 2 * outElems)
        k_copy<<<(outElems / 4 + 255) / 256, 256>>>(lidar, out + outElems,
                                                    outElems / 4);
}

// round 12
// speedup vs baseline: 1.1850x; 1.0634x over previous
#include <cuda_runtime.h>
#include <cstdint>

namespace {
constexpr int B_ = 8, N_ = 1024, DIM = 512, H_ = 8, DH = 64, INNER = 512, G = 64;
constexpr float SCALE = 0.125f;
constexpr float LOG2E = 1.4426950408889634f;
}

// Scratch (device globals — allocation-free rule)
__device__ float g_q[(size_t)G * N_ * DH];
__device__ float g_k[(size_t)G * N_ * DH];
__device__ float g_v[(size_t)G * N_ * DH];
__device__ float g_y[(size_t)B_ * N_ * INNER];
__device__ float g_ml[G * N_];   // log2-domain lidar logit upper bound
__device__ float g_isl[G * N_];  // 1 / sum exp2(lidar - bound)
__device__ float g_mi[G * N_];   // per-row upper bound of blended logit (log2)
__device__ float g_w2[DIM * INNER];
__device__ float g_b2[DIM];
__device__ float g_oacc[2 * (size_t)G * N_ * DH];  // split-KV partial O
__device__ float g_lacc[2 * G * N_];               // split-KV partial row sums

// ---------------------------------------------------------------------------
// helpers
// ---------------------------------------------------------------------------
__device__ __forceinline__ float cvt_tf32f(float x) {
    unsigned r;
    asm("cvt.rna.tf32.f32 %0, %1;" : "=r"(r) : "f"(x));
    return __uint_as_float(r);
}
__device__ __forceinline__ float ex2f(float x) {
    float y;
    asm("ex2.approx.f32 %0, %1;" : "=f"(y) : "f"(x));
    return y;
}

__device__ __forceinline__ void mma8(float* d, const unsigned* a, const unsigned* b) {
    asm("mma.sync.aligned.m16n8k8.row.col.f32.tf32.tf32.f32 "
        "{%0,%1,%2,%3}, {%4,%5,%6,%7}, {%8,%9}, {%0,%1,%2,%3};"
        : "+f"(d[0]), "+f"(d[1]), "+f"(d[2]), "+f"(d[3])
        : "r"(a[0]), "r"(a[1]), "r"(a[2]), "r"(a[3]), "r"(b[0]), "r"(b[1]));
}

__device__ __forceinline__ int swz(int r) { return ((r & 3) << 1) ^ (r & 4); }

template <int MT, int NT, int WARPS_N, int ASTR, int BSTR>
__device__ __forceinline__ void mma_slab_p(const float* As, const float* Bs,
                                           int warp, int g8, int t4,
                                           float (&acc)[MT][NT][4]) {
    const int wm = warp / WARPS_N, wn = warp % WARPS_N;
    const int po = (2 * t4) ^ swz(g8);
#pragma unroll
    for (int ks = 0; ks < 4; ks++) {
        const int off = ks * 8 + po;
        unsigned af[MT][4], bf[NT][2];
#pragma unroll
        for (int mt = 0; mt < MT; mt++) {
            int r = wm * (MT * 16) + mt * 16 + g8;
            float2 lo = *(const float2*)&As[r * ASTR + off];
            float2 hi = *(const float2*)&As[(r + 8) * ASTR + off];
            af[mt][0] = __float_as_uint(lo.x);
            af[mt][1] = __float_as_uint(hi.x);
            af[mt][2] = __float_as_uint(lo.y);
            af[mt][3] = __float_as_uint(hi.y);
        }
#pragma unroll
        for (int nt = 0; nt < NT; nt++) {
            int n = wn * (NT * 8) + nt * 8 + g8;
            float2 bv = *(const float2*)&Bs[n * BSTR + off];
            bf[nt][0] = __float_as_uint(bv.x);
            bf[nt][1] = __float_as_uint(bv.y);
        }
#pragma unroll
        for (int mt = 0; mt < MT; mt++)
#pragma unroll
            for (int nt = 0; nt < NT; nt++)
                mma8(acc[mt][nt], af[mt], bf[nt]);
    }
}

// PV: A = Ps (permuted, stride 136), B = Vs (k-major, stride 72). K=32 per call.
__device__ __forceinline__ void mma_pv(const float* Ps_, const float* Vs_,
                                       int warp, int g8, int t4,
                                       float (&acc)[2][4][4]) {
    const int wm2 = warp >> 1, wn2 = warp & 1;
    const int po = (2 * t4) ^ swz(g8);
#pragma unroll
    for (int ks = 0; ks < 4; ks++) {
        const int off = ks * 8 + po;
        const int c = ks * 8 + t4;
        unsigned af[2][4], bf[4][2];
#pragma unroll
        for (int mt = 0; mt < 2; mt++) {
            int r = wm2 * 32 + mt * 16 + g8;
            float2 lo = *(const float2*)&Ps_[r * 136 + off];
            float2 hi = *(const float2*)&Ps_[(r + 8) * 136 + off];
            af[mt][0] = __float_as_uint(lo.x);
            af[mt][1] = __float_as_uint(hi.x);
            af[mt][2] = __float_as_uint(lo.y);
            af[mt][3] = __float_as_uint(hi.y);
        }
#pragma unroll
        for (int nt = 0; nt < 4; nt++) {
            int n = wn2 * 32 + nt * 8 + g8;
            bf[nt][0] = __float_as_uint(Vs_[c * 72 + n]);
            bf[nt][1] = __float_as_uint(Vs_[(c + 4) * 72 + n]);
        }
#pragma unroll
        for (int mt = 0; mt < 2; mt++)
#pragma unroll
            for (int nt = 0; nt < 4; nt++)
                mma8(acc[mt][nt], af[mt], bf[nt]);
    }
}

struct R4T { float4 a[4]; };
__device__ __forceinline__ void ldg4(R4T& r, const float* g, int ld) {
    const int t = threadIdx.x;
    const int rr = t >> 3, c4 = (t & 7) * 4;
#pragma unroll
    for (int p = 0; p < 4; p++)
        r.a[p] = *(const float4*)(g + (size_t)(rr + p * 32) * ld + c4);
}
template <int STR>
__device__ __forceinline__ void sts4p(float* S, const R4T& r, float scale) {
    const int t = threadIdx.x;
    const int rr = t >> 3, c4 = (t & 7) * 4;
    const int start = (c4 & 24) + ((c4 & 4) ? 1 : 0);
#pragma unroll
    for (int p = 0; p < 4; p++) {
        int row = rr + p * 32;
        int sw = swz(row);
        float4 v = r.a[p];
        float* rp = S + row * STR;
        rp[(start + 0) ^ sw] = cvt_tf32f(v.x * scale);
        rp[(start + 2) ^ sw] = cvt_tf32f(v.y * scale);
        rp[(start + 4) ^ sw] = cvt_tf32f(v.z * scale);
        rp[(start + 6) ^ sw] = cvt_tf32f(v.w * scale);
    }
}

// ---------------------------------------------------------------------------
// K1: qkv = x @ w_qkv^T  -> head-major q/k/v  (double-buffered HMMA)
// ---------------------------------------------------------------------------
__global__ __launch_bounds__(256) void k_qkv(const float* __restrict__ x,
                                             const float* __restrict__ w) {
    __shared__ float As[2][128 * 40], Bs[2][128 * 40];
    const int t = threadIdx.x, warp = t >> 5, lane = t & 31;
    const int g8 = lane >> 2, t4 = lane & 3;
    const int n0 = blockIdx.x * 128, m0 = blockIdx.y * 128;
    float acc[4][4][4] = {};
    R4T ra, rb;
    ldg4(ra, x + (size_t)m0 * DIM, DIM);
    ldg4(rb, w + (size_t)n0 * DIM, DIM);
    sts4p<40>(As[0], ra, 1.f);
    sts4p<40>(Bs[0], rb, 1.f);
    __syncthreads();
    int cur = 0;
    for (int k0 = 32; k0 < DIM; k0 += 32) {
        ldg4(ra, x + (size_t)m0 * DIM + k0, DIM);
        ldg4(rb, w + (size_t)n0 * DIM + k0, DIM);
        mma_slab_p<4, 4, 4, 40, 40>(As[cur], Bs[cur], warp, g8, t4, acc);
        sts4p<40>(As[cur ^ 1], ra, 1.f);
        sts4p<40>(Bs[cur ^ 1], rb, 1.f);
        __syncthreads();
        cur ^= 1;
    }
    mma_slab_p<4, 4, 4, 40, 40>(As[cur], Bs[cur], warp, g8, t4, acc);
    const int wm = warp >> 2, wn = warp & 3;
#pragma unroll
    for (int mt = 0; mt < 4; mt++)
#pragma unroll
        for (int nt = 0; nt < 4; nt++) {
            int col = n0 + wn * 32 + nt * 8 + 2 * t4;
            int part = col >> 9, h = (col >> 6) & 7, d = col & 63;
            float* dst = part == 0 ? g_q : (part == 1 ? g_k : g_v);
#pragma unroll
            for (int half = 0; half < 2; half++) {
                int row = m0 + wm * 64 + mt * 16 + g8 + half * 8;
                int b = row >> 10, n = row & 1023;
                float2 val = half ? make_float2(acc[mt][nt][2], acc[mt][nt][3])
                                  : make_float2(acc[mt][nt][0], acc[mt][nt][1]);
                *(float2*)&dst[((size_t)((b * 8 + h) * 1024 + n)) * 64 + d] = val;
            }
        }
}

// ---------------------------------------------------------------------------
// K1b (merged bounds): y==0 -> blended-logit bound from q/k norms (g_mi).
//                      y==1 -> lidar logit bound from lidar norms (g_ml).
// ---------------------------------------------------------------------------
__global__ __launch_bounds__(256) void k_bounds(const float* __restrict__ conv_w,
                                                const float* __restrict__ lidar) {
    __shared__ float nrm[1024];
    __shared__ float red[8];
    __shared__ float smax;
    const int g = blockIdx.x, t = threadIdx.x;
    const int b = g >> 3, h = g & 7;
    if (blockIdx.y == 0) {
        // --- blended logit bound: |c0*SCALE*log2e| * ||q_i|| * max||k_j|| + max(c1*log2e,0)
        const float* kb = g_k + (size_t)g * N_ * DH;
        float mx = 0.f;
        for (int j = t; j < N_; j += 256) {
            const float4* r4 = (const float4*)(kb + (size_t)j * DH);
            float s = 0.f;
#pragma unroll
            for (int q = 0; q < 16; q++) {
                float4 v = r4[q];
                s += v.x * v.x + v.y * v.y + v.z * v.z + v.w * v.w;
            }
            mx = fmaxf(mx, s);
        }
        for (int o = 16; o; o >>= 1) mx = fmaxf(mx, __shfl_xor_sync(~0u, mx, o));
        if ((t & 31) == 0) red[t >> 5] = mx;
        __syncthreads();
        if (t == 0) {
            float m = red[0];
#pragma unroll
            for (int w = 1; w < 8; w++) m = fmaxf(m, red[w]);
            smax = m;
        }
        __syncthreads();
        const float maxkk = smax;
        const float c0a = fabsf(conv_w[0]) * SCALE * LOG2E;
        const float c1L = conv_w[1] * LOG2E;
        const float* qb = g_q + (size_t)g * N_ * DH;
        for (int i = t; i < N_; i += 256) {
            const float4* r4 = (const float4*)(qb + (size_t)i * DH);
            float s = 0.f;
#pragma unroll
            for (int q = 0; q < 16; q++) {
                float4 v = r4[q];
                s += v.x * v.x + v.y * v.y + v.z * v.z + v.w * v.w;
            }
            g_mi[g * N_ + i] = c0a * sqrtf(s * maxkk) + fmaxf(c1L, 0.f);
        }
    } else {
        // --- lidar logit bound: SCALE*log2e * ||lid_i|| * max||lid_j||
        const float* base = lidar + (size_t)b * N_ * INNER + h * 64;
        for (int i = t; i < N_; i += 256) {
            const float4* r4 = (const float4*)(base + (size_t)i * INNER);
            float s = 0.f;
#pragma unroll
            for (int q = 0; q < 16; q++) {
                float4 v = r4[q];
                s += v.x * v.x + v.y * v.y + v.z * v.z + v.w * v.w;
            }
            nrm[i] = sqrtf(s);
        }
        __syncthreads();
        float mx = 0.f;
        for (int i = t; i < N_; i += 256) mx = fmaxf(mx, nrm[i]);
        for (int o = 16; o; o >>= 1) mx = fmaxf(mx, __shfl_xor_sync(~0u, mx, o));
        if ((t & 31) == 0) red[t >> 5] = mx;
        __syncthreads();
        if (t == 0) {
            float m = red[0];
#pragma unroll
            for (int w = 1; w < 8; w++) m = fmaxf(m, red[w]);
            smax = m;
        }
        __syncthreads();
        const float c = SCALE * LOG2E * smax;
        for (int i = t; i < N_; i += 256)
            g_ml[g * N_ + i] = c * nrm[i];
    }
}

// ---------------------------------------------------------------------------
// K2 (lstats v2): lidar row sums with fixed bound — no online reductions.
// ---------------------------------------------------------------------------
__global__ __launch_bounds__(256) void k_lstats(const float* __restrict__ lidar) {
    __shared__ float AliL0[128 * 40], AliL1[128 * 40];
    __shared__ float Bs0[128 * 40], Bs1[128 * 40];
    __shared__ float mls[128];
    __shared__ float red[512];
    const int t = threadIdx.x, warp = t >> 5, lane = t & 31;
    const int g8 = lane >> 2, t4 = lane & 3;
    const int gidx = blockIdx.y, b = gidx >> 3, h = gidx & 7;
    const int i0 = blockIdx.x * 128;
    const float* base = lidar + (size_t)b * N_ * INNER + h * 64;
    const int wm = warp >> 2, wn = warp & 3;
    R4T ra, rb;
    ldg4(ra, base + (size_t)i0 * INNER, INNER);
    sts4p<40>(AliL0, ra, SCALE * LOG2E);
    ldg4(ra, base + (size_t)i0 * INNER + 32, INNER);
    sts4p<40>(AliL1, ra, SCALE * LOG2E);
    if (t < 128) mls[t] = g_ml[gidx * N_ + i0 + t];
    ldg4(ra, base, INNER);
    ldg4(rb, base + 32, INNER);
    __syncthreads();
    float lp[4][2] = {};
    for (int jt = 0; jt < 8; jt++) {
        float acc[4][4][4] = {};
        sts4p<40>(Bs0, ra, 1.f);
        sts4p<40>(Bs1, rb, 1.f);
        {
            const float* nxt = base + (size_t)(((jt + 1) & 7) * 128) * INNER;
            ldg4(ra, nxt, INNER);
            ldg4(rb, nxt + 32, INNER);
        }
        __syncthreads();
        mma_slab_p<4, 4, 4, 40, 40>(AliL0, Bs0, warp, g8, t4, acc);
        mma_slab_p<4, 4, 4, 40, 40>(AliL1, Bs1, warp, g8, t4, acc);
#pragma unroll
        for (int mt = 0; mt < 4; mt++) {
            int r = wm * 64 + mt * 16 + g8;
            float mn0 = mls[r], mn1 = mls[r + 8];
            float s0 = 0.f, s1 = 0.f;
#pragma unroll
            for (int nt = 0; nt < 4; nt++) {
                s0 += ex2f(acc[mt][nt][0] - mn0) + ex2f(acc[mt][nt][1] - mn0);
                s1 += ex2f(acc[mt][nt][2] - mn1) + ex2f(acc[mt][nt][3] - mn1);
            }
            lp[mt][0] += s0; lp[mt][1] += s1;
        }
        __syncthreads();
    }
#pragma unroll
    for (int mt = 0; mt < 4; mt++) {
        float s0 = lp[mt][0], s1 = lp[mt][1];
#pragma unroll
        for (int off = 1; off <= 2; off <<= 1) {
            s0 += __shfl_xor_sync(~0u, s0, off);
            s1 += __shfl_xor_sync(~0u, s1, off);
        }
        if (t4 == 0) {
            red[wn * 128 + wm * 64 + mt * 16 + g8] = s0;
            red[wn * 128 + wm * 64 + mt * 16 + g8 + 8] = s1;
        }
    }
    __syncthreads();
    if (t < 128)
        g_isl[gidx * N_ + i0 + t] =
            1.0f / (red[t] + red[128 + t] + red[256 + t] + red[384 + t]);
}

// ---------------------------------------------------------------------------
// K3 (flash, split-KV): each CTA handles half the j range; writes partial
// unnormalized O + partial row sums. 6 barriers/iter, no in-loop reductions.
// ---------------------------------------------------------------------------
__global__ __launch_bounds__(256, 1) void k_flash(const float* __restrict__ lidar,
                                                  const float* __restrict__ conv_w) {
    extern __shared__ float sm[];
    float* AliL0 = sm;
    float* AliL1 = sm + 5120;
    float* AliQ0 = sm + 10240;
    float* AliQ1 = sm + 15360;
    float* Bs    = sm + 20480;            // 128*40 (slab-even B)
    float* Vs    = sm + 25600;            // 128*72 (slab-odd B, then V)
    float* Ps    = sm + 34816;            // 128*136
    float* mls   = sm + 52224;
    float* isls  = mls + 128;
    float* m_s   = isls + 128;            // fixed per-row bound
    float* red   = m_s + 128;             // 4*128

    const int t = threadIdx.x, warp = t >> 5, lane = t & 31;
    const int g8 = lane >> 2, t4 = lane & 3;
    const int gidx = blockIdx.y, i0 = blockIdx.x * 128;
    const int jh = blockIdx.z;
    const int b = gidx >> 3, h = gidx & 7;
    const float c0s = conv_w[0] * SCALE * LOG2E;
    const float c1L = conv_w[1] * LOG2E;
    const int wm = warp >> 2, wn = warp & 3;
    const int wm2 = warp >> 1, wn2 = warp & 1;

    if (t < 128) {
        mls[t] = g_ml[gidx * N_ + i0 + t];
        isls[t] = g_isl[gidx * N_ + i0 + t];
        m_s[t] = g_mi[gidx * N_ + i0 + t];
    }
    const float* lbase = lidar + (size_t)b * N_ * INNER + h * 64;
    const float* qb = g_q + (size_t)gidx * N_ * DH;
    const float* kb = g_k + (size_t)gidx * N_ * DH;
    const float* vb = g_v + (size_t)gidx * N_ * DH;

    R4T ra, rb;
    ldg4(ra, lbase + (size_t)i0 * INNER, INNER);      sts4p<40>(AliL0, ra, SCALE * LOG2E);
    ldg4(ra, lbase + (size_t)i0 * INNER + 32, INNER); sts4p<40>(AliL1, ra, SCALE * LOG2E);
    ldg4(ra, qb + (size_t)i0 * DH, DH);               sts4p<40>(AliQ0, ra, c0s);
    ldg4(ra, qb + (size_t)i0 * DH + 32, DH);          sts4p<40>(AliQ1, ra, c0s);
    const int jstart = jh * 512;
    ldg4(ra, lbase + (size_t)jstart * INNER, INNER);
    ldg4(rb, lbase + (size_t)jstart * INNER + 32, INNER);
    __syncthreads();

    float acc_o[2][4][4] = {};
    float lp[4][2] = {};
    float4 vreg[8];

    const int vjr = t >> 2, vdc = (t & 3) * 16;

    for (int j0 = jstart; j0 < jstart + 512; j0 += 128) {
        float acc[4][4][4] = {};
        sts4p<40>(Bs, ra, 1.f);
        sts4p<72>(Vs, rb, 1.f);
        ldg4(ra, kb + (size_t)j0 * DH, DH);
        ldg4(rb, kb + (size_t)j0 * DH + 32, DH);
        __syncthreads();                               // B
        mma_slab_p<4, 4, 4, 40, 40>(AliL0, Bs, warp, g8, t4, acc);
        mma_slab_p<4, 4, 4, 40, 72>(AliL1, Vs, warp, g8, t4, acc);
#pragma unroll
        for (int mt = 0; mt < 4; mt++) {
            int r = wm * 64 + mt * 16 + g8;
            float m0v = mls[r], i0v = isls[r] * c1L;
            float m1v = mls[r + 8], i1v = isls[r + 8] * c1L;
#pragma unroll
            for (int nt = 0; nt < 4; nt++) {
                acc[mt][nt][0] = i0v * ex2f(acc[mt][nt][0] - m0v);
                acc[mt][nt][1] = i0v * ex2f(acc[mt][nt][1] - m0v);
                acc[mt][nt][2] = i1v * ex2f(acc[mt][nt][2] - m1v);
                acc[mt][nt][3] = i1v * ex2f(acc[mt][nt][3] - m1v);
            }
        }
        __syncthreads();                               // C
        sts4p<40>(Bs, ra, 1.f);
        sts4p<72>(Vs, rb, 1.f);
        {
            const float* src = vb + (size_t)(j0 + vjr) * DH + vdc;
#pragma unroll
            for (int q = 0; q < 4; q++) vreg[q] = *(const float4*)(src + q * 4);
            src += (size_t)64 * DH;
#pragma unroll
            for (int q = 0; q < 4; q++) vreg[4 + q] = *(const float4*)(src + q * 4);
        }
        __syncthreads();                               // D
        mma_slab_p<4, 4, 4, 40, 40>(AliQ0, Bs, warp, g8, t4, acc);
        mma_slab_p<4, 4, 4, 40, 72>(AliQ1, Vs, warp, g8, t4, acc);
        {
            const int swp = swz(g8);
            const int pbase = ((2 * t4) & 3) * 2 + ((t4 & 2) ? 1 : 0);
#pragma unroll
            for (int mt = 0; mt < 4; mt++) {
                int r = wm * 64 + mt * 16 + g8;
                float mn0 = m_s[r], mn1 = m_s[r + 8];
                float s0 = 0.f, s1 = 0.f;
#pragma unroll
                for (int nt = 0; nt < 4; nt++) {
                    float p0 = ex2f(acc[mt][nt][0] - mn0);
                    float p1 = ex2f(acc[mt][nt][1] - mn0);
                    float p2 = ex2f(acc[mt][nt][2] - mn1);
                    float p3 = ex2f(acc[mt][nt][3] - mn1);
                    s0 += p0 + p1; s1 += p2 + p3;
                    int gp = wn * 32 + nt * 8;
                    float* rowA = Ps + r * 136 + gp;
                    float* rowB = Ps + (r + 8) * 136 + gp;
                    rowA[(pbase + 0) ^ swp] = cvt_tf32f(p0);
                    rowA[(pbase + 2) ^ swp] = cvt_tf32f(p1);
                    rowB[(pbase + 0) ^ swp] = cvt_tf32f(p2);
                    rowB[(pbase + 2) ^ swp] = cvt_tf32f(p3);
                }
                lp[mt][0] += s0; lp[mt][1] += s1;
            }
        }
        __syncthreads();                               // E (Vs free)
#pragma unroll
        for (int p = 0; p < 2; p++) {
            int jj = vjr + p * 64;
#pragma unroll
            for (int q = 0; q < 4; q++) {
                float4 v = vreg[p * 4 + q];
                float4 o;
                o.x = cvt_tf32f(v.x); o.y = cvt_tf32f(v.y);
                o.z = cvt_tf32f(v.z); o.w = cvt_tf32f(v.w);
                *(float4*)(Vs + jj * 72 + vdc + q * 4) = o;
            }
        }
        {
            const float* nxt = lbase + (size_t)((j0 + 128) & (N_ - 1)) * INNER;
            ldg4(ra, nxt, INNER);
            ldg4(rb, nxt + 32, INNER);
        }
        __syncthreads();                               // F
#pragma unroll
        for (int slab = 0; slab < 4; slab++)
            mma_pv(Ps + slab * 32, Vs + (size_t)slab * 32 * 72,
                   warp, g8, t4, acc_o);
        __syncthreads();                               // A (next iter)
    }
    // final partial row-sum reduction
#pragma unroll
    for (int mt = 0; mt < 4; mt++) {
        float s0 = lp[mt][0], s1 = lp[mt][1];
#pragma unroll
        for (int off = 1; off <= 2; off <<= 1) {
            s0 += __shfl_xor_sync(~0u, s0, off);
            s1 += __shfl_xor_sync(~0u, s1, off);
        }
        if (t4 == 0) {
            red[wn * 128 + wm * 64 + mt * 16 + g8] = s0;
            red[wn * 128 + wm * 64 + mt * 16 + g8 + 8] = s1;
        }
    }
    __syncthreads();
    if (t < 128)
        g_lacc[jh * G * N_ + gidx * N_ + i0 + t] =
            red[t] + red[128 + t] + red[256 + t] + red[384 + t];
    // write unnormalized partial O
    float* ob = g_oacc + (size_t)jh * G * N_ * DH + ((size_t)gidx * N_ + i0) * DH;
#pragma unroll
    for (int mt = 0; mt < 2; mt++) {
        int r = wm2 * 32 + mt * 16 + g8;
#pragma unroll
        for (int nt = 0; nt < 4; nt++) {
            int d = wn2 * 32 + nt * 8 + 2 * t4;
            *(float2*)&ob[(size_t)r * DH + d] =
                make_float2(acc_o[mt][nt][0], acc_o[mt][nt][1]);
            *(float2*)&ob[(size_t)(r + 8) * DH + d] =
                make_float2(acc_o[mt][nt][2], acc_o[mt][nt][3]);
        }
    }
}

// ---------------------------------------------------------------------------
// K3b: combine split-KV partials -> g_y (scattered layout)
// ---------------------------------------------------------------------------
__global__ __launch_bounds__(256) void k_combine() {
    int idx = blockIdx.x * 256 + threadIdx.x;          // one float4 each
    int g = idx >> 14;                                  // N*DH/4 = 16384 per g
    int rem = idx & 16383;
    int n = rem >> 4;
    int d4 = (rem & 15) * 4;
    float l = g_lacc[g * N_ + n] + g_lacc[G * N_ + g * N_ + n];
    float inv = 1.0f / l;
    size_t off = ((size_t)g * N_ + n) * DH + d4;
    float4 o0 = *(const float4*)&g_oacc[off];
    float4 o1 = *(const float4*)&g_oacc[(size_t)G * N_ * DH + off];
    int b = g >> 3, h = g & 7;
    float* dst = g_y + ((size_t)b * N_ + n) * INNER + h * 64 + d4;
    *(float4*)dst = make_float4((o0.x + o1.x) * inv, (o0.y + o1.y) * inv,
                                (o0.z + o1.z) * inv, (o0.w + o1.w) * inv);
}

// ---------------------------------------------------------------------------
// K4: out = y @ W2^T + bias2  (double-buffered HMMA)
// ---------------------------------------------------------------------------
__global__ __launch_bounds__(256) void k_out(float* __restrict__ out) {
    __shared__ float As[2][128 * 40], Bs[2][128 * 40];
    const int t = threadIdx.x, warp = t >> 5, lane = t & 31;
    const int g8 = lane >> 2, t4 = lane & 3;
    const int n0 = blockIdx.x * 128, m0 = blockIdx.y * 128;
    float acc[4][4][4] = {};
    R4T ra, rb;
    ldg4(ra, g_y + (size_t)m0 * INNER, INNER);
    ldg4(rb, g_w2 + (size_t)n0 * INNER, INNER);
    sts4p<40>(As[0], ra, 1.f);
    sts4p<40>(Bs[0], rb, 1.f);
    __syncthreads();
    int cur = 0;
    for (int k0 = 32; k0 < INNER; k0 += 32) {
        ldg4(ra, g_y + (size_t)m0 * INNER + k0, INNER);
        ldg4(rb, g_w2 + (size_t)n0 * INNER + k0, INNER);
        mma_slab_p<4, 4, 4, 40, 40>(As[cur], Bs[cur], warp, g8, t4, acc);
        sts4p<40>(As[cur ^ 1], ra, 1.f);
        sts4p<40>(Bs[cur ^ 1], rb, 1.f);
        __syncthreads();
        cur ^= 1;
    }
    mma_slab_p<4, 4, 4, 40, 40>(As[cur], Bs[cur], warp, g8, t4, acc);
    const int wm = warp >> 2, wn = warp & 3;
#pragma unroll
    for (int mt = 0; mt < 4; mt++)
#pragma unroll
        for (int nt = 0; nt < 4; nt++) {
            int col = n0 + wn * 32 + nt * 8 + 2 * t4;
            float b0 = g_b2[col], b1 = g_b2[col + 1];
            int r = m0 + wm * 64 + mt * 16 + g8;
            *(float2*)&out[(size_t)r * DIM + col] =
                make_float2(acc[mt][nt][0] + b0, acc[mt][nt][1] + b1);
            *(float2*)&out[(size_t)(r + 8) * DIM + col] =
                make_float2(acc[mt][nt][2] + b0, acc[mt][nt][3] + b1);
        }
}

// ---------------------------------------------------------------------------
// Precompute: W2 = Wout(.,h-block) @ Wm ; bias2 = b_out + Wout b_merge~
// ---------------------------------------------------------------------------
__global__ __launch_bounds__(256) void k_w2(const float* __restrict__ w_merge,
                                            const float* __restrict__ w_out) {
    __shared__ float wm[64 * 64];
    const int t = threadIdx.x;
    for (int i = t; i < 4096; i += 256) wm[i] = w_merge[i];
    __syncthreads();
    int idx = blockIdx.x * 256 + t;
    int c = idx >> 9, i = idx & 511;
    int h = i >> 6, d = i & 63;
    const float* wo = w_out + (size_t)c * INNER + h * 64;
    float s = 0.f;
#pragma unroll 8
    for (int dp = 0; dp < 64; dp++) s += wo[dp] * wm[dp * 64 + d];
    g_w2[idx] = s;
}

__global__ __launch_bounds__(256) void k_bias2(const float* __restrict__ w_out,
                                               const float* __restrict__ b_merge,
                                               const float* __restrict__ b_out) {
    int c = blockIdx.x * 8 + (threadIdx.x >> 5);
    int lane = threadIdx.x & 31;
    float s = 0.f;
    for (int i = lane; i < INNER; i += 32)
        s += w_out[(size_t)c * INNER + i] * b_merge[i & 63];
    for (int o = 16; o; o >>= 1) s += __shfl_xor_sync(~0u, s, o);
    if (lane == 0) g_b2[c] = b_out[c] + s;
}

__global__ __launch_bounds__(256) void k_copy(const float* __restrict__ src,
                                              float* __restrict__ dst, int n4) {
    int i = blockIdx.x * blockDim.x + threadIdx.x;
    if (i < n4) ((float4*)dst)[i] = ((const float4*)src)[i];
}

extern "C" void kernel_launch(void* const* d_in, const int* in_sizes, int n_in,
                              void* d_out, int out_size) {
    const float* x       = (const float*)d_in[0];
    const float* lidar   = (const float*)d_in[1];
    const float* w_qkv   = (const float*)d_in[2];
    const float* w_merge = (const float*)d_in[3];
    const float* b_merge = (const float*)d_in[4];
    const float* w_out   = (const float*)d_in[5];
    const float* b_out   = (const float*)d_in[6];
    const float* conv_w  = (const float*)d_in[7];
    float* out = (float*)d_out;

    const int flashSmem = (52224 + 3 * 128 + 512) * 4;
    cudaFuncSetAttribute(k_flash, cudaFuncAttributeMaxDynamicSharedMemorySize,
                         flashSmem);

    // launch order keeps k_flash 4th (ncu captures launch #4)
    k_qkv<<<dim3(12, 64), 256>>>(x, w_qkv);
    k_bounds<<<dim3(G, 2), 256>>>(conv_w, lidar);
    k_lstats<<<dim3(8, G), 256>>>(lidar);
    k_flash<<<dim3(8, G, 2), 256, flashSmem>>>(lidar, conv_w);
    k_w2<<<1024, 256>>>(w_merge, w_out);
    k_bias2<<<64, 256>>>(w_out, b_merge, b_out);
    k_combine<<<4096, 256>>>();
    k_out<<<dim3(4, 64), 256>>>(out);

    const int outElems = B_ * N_ * DIM;
    if (out_size >= 2 * outElems)
        k_copy<<<(outElems / 4 + 255) / 256, 256>>>(lidar, out + outElems,
                                                    outElems / 4);
}

// round 13
// speedup vs baseline: 1.6180x; 1.3654x over previous
#include <cuda_runtime.h>
#include <cuda_fp16.h>
#include <cstdint>

namespace {
constexpr int B_ = 8, N_ = 1024, DIM = 512, H_ = 8, DH = 64, INNER = 512, G = 64;
constexpr float SCALE = 0.125f;
constexpr float LOG2E = 1.4426950408889634f;
}

// Scratch (device globals — allocation-free rule)
__device__ float g_q[(size_t)G * N_ * DH];
__device__ float g_k[(size_t)G * N_ * DH];
__device__ float g_vT[(size_t)G * DH * N_];        // V transposed: [g][d][j]
__device__ float g_y[(size_t)B_ * N_ * INNER];
__device__ float g_ml[G * N_];   // log2-domain lidar logit upper bound
__device__ float g_isl[G * N_];  // 1 / sum exp2(lidar - bound)
__device__ float g_mi[G * N_];   // per-row upper bound of blended logit (log2)
__device__ float g_w2[DIM * INNER];
__device__ float g_b2[DIM];
__device__ float g_oacc[2 * (size_t)G * N_ * DH];  // split-KV partial O
__device__ float g_lacc[2 * G * N_];               // split-KV partial row sums

// ---------------------------------------------------------------------------
// helpers
// ---------------------------------------------------------------------------
__device__ __forceinline__ float ex2f(float x) {
    float y;
    asm("ex2.approx.f32 %0, %1;" : "=f"(y) : "f"(x));
    return y;
}

// fp16 mma m16n8k16: D(f32) += A(f16,row) * B(f16,col)
__device__ __forceinline__ void mma16(float* d, const unsigned* a,
                                      const unsigned* b) {
    asm("mma.sync.aligned.m16n8k16.row.col.f32.f16.f16.f32 "
        "{%0,%1,%2,%3}, {%4,%5,%6,%7}, {%8,%9}, {%0,%1,%2,%3};"
        : "+f"(d[0]), "+f"(d[1]), "+f"(d[2]), "+f"(d[3])
        : "r"(a[0]), "r"(a[1]), "r"(a[2]), "r"(a[3]), "r"(b[0]), "r"(b[1]));
}

// fp16 tile mma. A: [rows][ASTR] halves (k contiguous), B: [n][BSTR] halves.
// Fragment pairs (2t4, 2t4+1) and (+8) are contiguous half2 -> b32 loads.
template <int MT, int NT, int WARPS_N, int KS, int ASTR, int BSTR>
__device__ __forceinline__ void mma_h(const __half* As, const __half* Bs,
                                      int warp, int g8, int t4,
                                      float (&acc)[MT][NT][4]) {
    const int wm = warp / WARPS_N, wn = warp % WARPS_N;
#pragma unroll
    for (int ks = 0; ks < KS; ks++) {
        const int base = ks * 16 + 2 * t4;
        unsigned af[MT][4], bf[NT][2];
#pragma unroll
        for (int mt = 0; mt < MT; mt++) {
            int r = wm * (MT * 16) + mt * 16 + g8;
            af[mt][0] = *(const unsigned*)&As[r * ASTR + base];
            af[mt][1] = *(const unsigned*)&As[(r + 8) * ASTR + base];
            af[mt][2] = *(const unsigned*)&As[r * ASTR + base + 8];
            af[mt][3] = *(const unsigned*)&As[(r + 8) * ASTR + base + 8];
        }
#pragma unroll
        for (int nt = 0; nt < NT; nt++) {
            int n = wn * (NT * 8) + nt * 8 + g8;
            bf[nt][0] = *(const unsigned*)&Bs[n * BSTR + base];
            bf[nt][1] = *(const unsigned*)&Bs[n * BSTR + base + 8];
        }
#pragma unroll
        for (int mt = 0; mt < MT; mt++)
#pragma unroll
            for (int nt = 0; nt < NT; nt++)
                mma16(acc[mt][nt], af[mt], bf[nt]);
    }
}

struct R4T { float4 a[4]; };
__device__ __forceinline__ void ldg4(R4T& r, const float* g, int ld) {
    const int t = threadIdx.x;
    const int rr = t >> 3, c4 = (t & 7) * 4;
#pragma unroll
    for (int p = 0; p < 4; p++)
        r.a[p] = *(const float4*)(g + (size_t)(rr + p * 32) * ld + c4);
}
// store 128x32 float tile into half tile at column offset COFF, stride STRH.
template <int STRH, int COFF>
__device__ __forceinline__ void sts4h(__half* S, const R4T& r, float scale) {
    const int t = threadIdx.x;
    const int rr = t >> 3, c4 = (t & 7) * 4;
#pragma unroll
    for (int p = 0; p < 4; p++) {
        int row = rr + p * 32;
        float4 v = r.a[p];
        __half* rp = S + row * STRH + COFF + c4;
        *(__half2*)rp = __floats2half2_rn(v.x * scale, v.y * scale);
        *(__half2*)(rp + 2) = __floats2half2_rn(v.z * scale, v.w * scale);
    }
}

// ---------------------------------------------------------------------------
// K1: qkv = x @ w_qkv^T -> head-major q/k + transposed vT  (fp16 HMMA)
// ---------------------------------------------------------------------------
__global__ __launch_bounds__(256) void k_qkv(const float* __restrict__ x,
                                             const float* __restrict__ w) {
    __shared__ __half As[2][128 * 40], Bs[2][128 * 40];
    const int t = threadIdx.x, warp = t >> 5, lane = t & 31;
    const int g8 = lane >> 2, t4 = lane & 3;
    const int n0 = blockIdx.x * 128, m0 = blockIdx.y * 128;
    float acc[4][4][4] = {};
    R4T ra, rb;
    ldg4(ra, x + (size_t)m0 * DIM, DIM);
    ldg4(rb, w + (size_t)n0 * DIM, DIM);
    sts4h<40, 0>(As[0], ra, 1.f);
    sts4h<40, 0>(Bs[0], rb, 1.f);
    __syncthreads();
    int cur = 0;
    for (int k0 = 32; k0 < DIM; k0 += 32) {
        ldg4(ra, x + (size_t)m0 * DIM + k0, DIM);
        ldg4(rb, w + (size_t)n0 * DIM + k0, DIM);
        mma_h<4, 4, 4, 2, 40, 40>(As[cur], Bs[cur], warp, g8, t4, acc);
        sts4h<40, 0>(As[cur ^ 1], ra, 1.f);
        sts4h<40, 0>(Bs[cur ^ 1], rb, 1.f);
        __syncthreads();
        cur ^= 1;
    }
    mma_h<4, 4, 4, 2, 40, 40>(As[cur], Bs[cur], warp, g8, t4, acc);
    const int wm = warp >> 2, wn = warp & 3;
#pragma unroll
    for (int mt = 0; mt < 4; mt++)
#pragma unroll
        for (int nt = 0; nt < 4; nt++) {
            int col = n0 + wn * 32 + nt * 8 + 2 * t4;
            int part = col >> 9, h = (col >> 6) & 7, d = col & 63;
#pragma unroll
            for (int half = 0; half < 2; half++) {
                int row = m0 + wm * 64 + mt * 16 + g8 + half * 8;
                int b = row >> 10, n = row & 1023;
                float2 val = half ? make_float2(acc[mt][nt][2], acc[mt][nt][3])
                                  : make_float2(acc[mt][nt][0], acc[mt][nt][1]);
                if (part == 2) {
                    float* dT = g_vT + ((size_t)((b * 8 + h) * 64 + d)) * 1024 + n;
                    dT[0] = val.x;
                    dT[1024] = val.y;
                } else {
                    float* dst = part == 0 ? g_q : g_k;
                    *(float2*)&dst[((size_t)((b * 8 + h) * 1024 + n)) * 64 + d] = val;
                }
            }
        }
}

// ---------------------------------------------------------------------------
// K1b (merged bounds): y==0 -> blended-logit bound (g_mi); y==1 -> lidar (g_ml)
// ---------------------------------------------------------------------------
__global__ __launch_bounds__(256) void k_bounds(const float* __restrict__ conv_w,
                                                const float* __restrict__ lidar) {
    __shared__ float nrm[1024];
    __shared__ float red[8];
    __shared__ float smax;
    const int g = blockIdx.x, t = threadIdx.x;
    const int b = g >> 3, h = g & 7;
    if (blockIdx.y == 0) {
        const float* kb = g_k + (size_t)g * N_ * DH;
        float mx = 0.f;
        for (int j = t; j < N_; j += 256) {
            const float4* r4 = (const float4*)(kb + (size_t)j * DH);
            float s = 0.f;
#pragma unroll
            for (int q = 0; q < 16; q++) {
                float4 v = r4[q];
                s += v.x * v.x + v.y * v.y + v.z * v.z + v.w * v.w;
            }
            mx = fmaxf(mx, s);
        }
        for (int o = 16; o; o >>= 1) mx = fmaxf(mx, __shfl_xor_sync(~0u, mx, o));
        if ((t & 31) == 0) red[t >> 5] = mx;
        __syncthreads();
        if (t == 0) {
            float m = red[0];
#pragma unroll
            for (int w = 1; w < 8; w++) m = fmaxf(m, red[w]);
            smax = m;
        }
        __syncthreads();
        const float maxkk = smax;
        const float c0a = fabsf(conv_w[0]) * SCALE * LOG2E;
        const float c1L = conv_w[1] * LOG2E;
        const float* qb = g_q + (size_t)g * N_ * DH;
        for (int i = t; i < N_; i += 256) {
            const float4* r4 = (const float4*)(qb + (size_t)i * DH);
            float s = 0.f;
#pragma unroll
            for (int q = 0; q < 16; q++) {
                float4 v = r4[q];
                s += v.x * v.x + v.y * v.y + v.z * v.z + v.w * v.w;
            }
            g_mi[g * N_ + i] = c0a * sqrtf(s * maxkk) + fmaxf(c1L, 0.f);
        }
    } else {
        const float* base = lidar + (size_t)b * N_ * INNER + h * 64;
        for (int i = t; i < N_; i += 256) {
            const float4* r4 = (const float4*)(base + (size_t)i * INNER);
            float s = 0.f;
#pragma unroll
            for (int q = 0; q < 16; q++) {
                float4 v = r4[q];
                s += v.x * v.x + v.y * v.y + v.z * v.z + v.w * v.w;
            }
            nrm[i] = sqrtf(s);
        }
        __syncthreads();
        float mx = 0.f;
        for (int i = t; i < N_; i += 256) mx = fmaxf(mx, nrm[i]);
        for (int o = 16; o; o >>= 1) mx = fmaxf(mx, __shfl_xor_sync(~0u, mx, o));
        if ((t & 31) == 0) red[t >> 5] = mx;
        __syncthreads();
        if (t == 0) {
            float m = red[0];
#pragma unroll
            for (int w = 1; w < 8; w++) m = fmaxf(m, red[w]);
            smax = m;
        }
        __syncthreads();
        const float c = SCALE * LOG2E * smax;
        for (int i = t; i < N_; i += 256)
            g_ml[g * N_ + i] = c * nrm[i];
    }
}

// ---------------------------------------------------------------------------
// K2 (lstats): lidar row sums with fixed bound. fp16, 1 sync/iter.
// ---------------------------------------------------------------------------
__global__ __launch_bounds__(256) void k_lstats(const float* __restrict__ lidar) {
    extern __shared__ __half smh[];
    __half* Ali = smh;                    // 128*72
    __half* BsA = smh + 9216;             // 2 x 128*72
    float* mls = (float*)(smh + 27648);
    float* red = mls + 128;               // 512
    const int t = threadIdx.x, warp = t >> 5, lane = t & 31;
    const int g8 = lane >> 2, t4 = lane & 3;
    const int gidx = blockIdx.y, b = gidx >> 3, h = gidx & 7;
    const int i0 = blockIdx.x * 128;
    const float* base = lidar + (size_t)b * N_ * INNER + h * 64;
    const int wm = warp >> 2, wn = warp & 3;
    R4T ra, rb;
    ldg4(ra, base + (size_t)i0 * INNER, INNER);
    sts4h<72, 0>(Ali, ra, SCALE * LOG2E);
    ldg4(ra, base + (size_t)i0 * INNER + 32, INNER);
    sts4h<72, 32>(Ali, ra, SCALE * LOG2E);
    if (t < 128) mls[t] = g_ml[gidx * N_ + i0 + t];
    ldg4(ra, base, INNER);
    ldg4(rb, base + 32, INNER);
    sts4h<72, 0>(BsA, ra, 1.f);
    sts4h<72, 32>(BsA, rb, 1.f);
    ldg4(ra, base + (size_t)128 * INNER, INNER);
    ldg4(rb, base + (size_t)128 * INNER + 32, INNER);
    __syncthreads();
    int cur = 0;
    float lp[4][2] = {};
    for (int jt = 0; jt < 8; jt++) {
        __half* bnext = BsA + (cur ^ 1) * 9216;
        sts4h<72, 0>(bnext, ra, 1.f);
        sts4h<72, 32>(bnext, rb, 1.f);
        {
            const float* nxt = base + (size_t)(((jt + 2) & 7) * 128) * INNER;
            ldg4(ra, nxt, INNER);
            ldg4(rb, nxt + 32, INNER);
        }
        float acc[4][4][4] = {};
        mma_h<4, 4, 4, 4, 72, 72>(Ali, BsA + cur * 9216, warp, g8, t4, acc);
#pragma unroll
        for (int mt = 0; mt < 4; mt++) {
            int r = wm * 64 + mt * 16 + g8;
            float mn0 = mls[r], mn1 = mls[r + 8];
            float s0 = 0.f, s1 = 0.f;
#pragma unroll
            for (int nt = 0; nt < 4; nt++) {
                s0 += ex2f(acc[mt][nt][0] - mn0) + ex2f(acc[mt][nt][1] - mn0);
                s1 += ex2f(acc[mt][nt][2] - mn1) + ex2f(acc[mt][nt][3] - mn1);
            }
            lp[mt][0] += s0; lp[mt][1] += s1;
        }
        __syncthreads();
        cur ^= 1;
    }
#pragma unroll
    for (int mt = 0; mt < 4; mt++) {
        float s0 = lp[mt][0], s1 = lp[mt][1];
#pragma unroll
        for (int off = 1; off <= 2; off <<= 1) {
            s0 += __shfl_xor_sync(~0u, s0, off);
            s1 += __shfl_xor_sync(~0u, s1, off);
        }
        if (t4 == 0) {
            red[wn * 128 + wm * 64 + mt * 16 + g8] = s0;
            red[wn * 128 + wm * 64 + mt * 16 + g8 + 8] = s1;
        }
    }
    __syncthreads();
    if (t < 128)
        g_isl[gidx * N_ + i0 + t] =
            1.0f / (red[t] + red[128 + t] + red[256 + t] + red[384 + t]);
}

// ---------------------------------------------------------------------------
// K3 (flash, split-KV, fp16): 3 barriers/iter, no in-loop reductions.
// ---------------------------------------------------------------------------
__global__ __launch_bounds__(256, 1) void k_flash(const float* __restrict__ lidar,
                                                  const float* __restrict__ conv_w) {
    extern __shared__ __half smh[];
    __half* AliL = smh;                   // 128*72
    __half* AliQ = smh + 9216;            // 128*72
    __half* Bs0  = smh + 18432;           // 128*72
    __half* Bs1  = smh + 27648;           // 128*72
    __half* Vs   = smh + 36864;           // 64*136 (d-major, j contiguous)
    __half* Ps   = smh + 45568;           // 128*136
    float* mls  = (float*)(smh + 62976);
    float* isls = mls + 128;
    float* m_s  = isls + 128;
    float* red  = m_s + 128;              // 512

    const int t = threadIdx.x, warp = t >> 5, lane = t & 31;
    const int g8 = lane >> 2, t4 = lane & 3;
    const int gidx = blockIdx.y, i0 = blockIdx.x * 128;
    const int jh = blockIdx.z;
    const int b = gidx >> 3, h = gidx & 7;
    const float c0s = conv_w[0] * SCALE * LOG2E;
    const float c1L = conv_w[1] * LOG2E;
    const int wm = warp >> 2, wn = warp & 3;
    const int wm2 = warp >> 1, wn2 = warp & 1;

    if (t < 128) {
        mls[t] = g_ml[gidx * N_ + i0 + t];
        isls[t] = g_isl[gidx * N_ + i0 + t];
        m_s[t] = g_mi[gidx * N_ + i0 + t];
    }
    const float* lbase = lidar + (size_t)b * N_ * INNER + h * 64;
    const float* qb = g_q + (size_t)gidx * N_ * DH;
    const float* kb = g_k + (size_t)gidx * N_ * DH;
    const float* vb = g_vT + (size_t)gidx * DH * N_;

    R4T ra, rb;
    ldg4(ra, lbase + (size_t)i0 * INNER, INNER);      sts4h<72, 0>(AliL, ra, SCALE * LOG2E);
    ldg4(ra, lbase + (size_t)i0 * INNER + 32, INNER); sts4h<72, 32>(AliL, ra, SCALE * LOG2E);
    ldg4(ra, qb + (size_t)i0 * DH, DH);               sts4h<72, 0>(AliQ, ra, c0s);
    ldg4(ra, qb + (size_t)i0 * DH + 32, DH);          sts4h<72, 32>(AliQ, ra, c0s);
    const int jstart = jh * 512;
    ldg4(ra, lbase + (size_t)jstart * INNER, INNER);
    ldg4(rb, lbase + (size_t)jstart * INNER + 32, INNER);
    sts4h<72, 0>(Bs0, ra, 1.f);
    sts4h<72, 32>(Bs0, rb, 1.f);
    ldg4(ra, kb + (size_t)jstart * DH, DH);
    ldg4(rb, kb + (size_t)jstart * DH + 32, DH);
    __syncthreads();

    float acc_o[2][4][4] = {};
    float lp[4][2] = {};
    float4 vreg[8];

    const int vd = t >> 2;                 // 0..63
    const int vj = (t & 3) * 4;            // j base within 16-group

    for (int j0 = jstart; j0 < jstart + 512; j0 += 128) {
        float acc[4][4][4] = {};
        // --- step 1: lidar mma (Bs0); stage k (Bs1); ldg V
        mma_h<4, 4, 4, 4, 72, 72>(AliL, Bs0, warp, g8, t4, acc);
#pragma unroll
        for (int mt = 0; mt < 4; mt++) {
            int r = wm * 64 + mt * 16 + g8;
            float m0v = mls[r], i0v = isls[r] * c1L;
            float m1v = mls[r + 8], i1v = isls[r + 8] * c1L;
#pragma unroll
            for (int nt = 0; nt < 4; nt++) {
                acc[mt][nt][0] = i0v * ex2f(acc[mt][nt][0] - m0v);
                acc[mt][nt][1] = i0v * ex2f(acc[mt][nt][1] - m0v);
                acc[mt][nt][2] = i1v * ex2f(acc[mt][nt][2] - m1v);
                acc[mt][nt][3] = i1v * ex2f(acc[mt][nt][3] - m1v);
            }
        }
        sts4h<72, 0>(Bs1, ra, 1.f);
        sts4h<72, 32>(Bs1, rb, 1.f);
        {
            const float* src = vb + (size_t)vd * N_ + j0 + vj;
#pragma unroll
            for (int q = 0; q < 8; q++)
                vreg[q] = *(const float4*)(src + q * 16);
        }
        __syncthreads();                               // (1)
        // --- step 2: qk mma (Bs1); P write; stage V; ldg next lidar
        mma_h<4, 4, 4, 4, 72, 72>(AliQ, Bs1, warp, g8, t4, acc);
#pragma unroll
        for (int mt = 0; mt < 4; mt++) {
            int r = wm * 64 + mt * 16 + g8;
            float mn0 = m_s[r], mn1 = m_s[r + 8];
            float s0 = 0.f, s1 = 0.f;
#pragma unroll
            for (int nt = 0; nt < 4; nt++) {
                float p0 = ex2f(acc[mt][nt][0] - mn0);
                float p1 = ex2f(acc[mt][nt][1] - mn0);
                float p2 = ex2f(acc[mt][nt][2] - mn1);
                float p3 = ex2f(acc[mt][nt][3] - mn1);
                s0 += p0 + p1; s1 += p2 + p3;
                int gp = wn * 32 + nt * 8 + 2 * t4;
                *(__half2*)&Ps[r * 136 + gp] = __floats2half2_rn(p0, p1);
                *(__half2*)&Ps[(r + 8) * 136 + gp] = __floats2half2_rn(p2, p3);
            }
            lp[mt][0] += s0; lp[mt][1] += s1;
        }
#pragma unroll
        for (int q = 0; q < 8; q++) {
            float4 v = vreg[q];
            __half* rp = Vs + vd * 136 + vj + q * 16;
            *(__half2*)rp = __floats2half2_rn(v.x, v.y);
            *(__half2*)(rp + 2) = __floats2half2_rn(v.z, v.w);
        }
        {
            const float* nxt = lbase + (size_t)((j0 + 128) & (N_ - 1)) * INNER;
            ldg4(ra, nxt, INNER);
            ldg4(rb, nxt + 32, INNER);
        }
        __syncthreads();                               // (2)
        // --- step 3: PV mma; stage next lidar (Bs0); ldg next k
        mma_h<2, 4, 2, 8, 136, 136>(Ps, Vs, warp, g8, t4, acc_o);
        sts4h<72, 0>(Bs0, ra, 1.f);
        sts4h<72, 32>(Bs0, rb, 1.f);
        {
            const float* nxt = kb + (size_t)((j0 + 128) & (N_ - 1)) * DH;
            ldg4(ra, nxt, DH);
            ldg4(rb, nxt + 32, DH);
        }
        __syncthreads();                               // (3)
    }
    // final partial row-sum reduction
#pragma unroll
    for (int mt = 0; mt < 4; mt++) {
        float s0 = lp[mt][0], s1 = lp[mt][1];
#pragma unroll
        for (int off = 1; off <= 2; off <<= 1) {
            s0 += __shfl_xor_sync(~0u, s0, off);
            s1 += __shfl_xor_sync(~0u, s1, off);
        }
        if (t4 == 0) {
            red[wn * 128 + wm * 64 + mt * 16 + g8] = s0;
            red[wn * 128 + wm * 64 + mt * 16 + g8 + 8] = s1;
        }
    }
    __syncthreads();
    if (t < 128)
        g_lacc[jh * G * N_ + gidx * N_ + i0 + t] =
            red[t] + red[128 + t] + red[256 + t] + red[384 + t];
    float* ob = g_oacc + (size_t)jh * G * N_ * DH + ((size_t)gidx * N_ + i0) * DH;
#pragma unroll
    for (int mt = 0; mt < 2; mt++) {
        int r = wm2 * 32 + mt * 16 + g8;
#pragma unroll
        for (int nt = 0; nt < 4; nt++) {
            int d = wn2 * 32 + nt * 8 + 2 * t4;
            *(float2*)&ob[(size_t)r * DH + d] =
                make_float2(acc_o[mt][nt][0], acc_o[mt][nt][1]);
            *(float2*)&ob[(size_t)(r + 8) * DH + d] =
                make_float2(acc_o[mt][nt][2], acc_o[mt][nt][3]);
        }
    }
}

// ---------------------------------------------------------------------------
// K3b: combine split-KV partials -> g_y (scattered layout)
// ---------------------------------------------------------------------------
__global__ __launch_bounds__(256) void k_combine() {
    int idx = blockIdx.x * 256 + threadIdx.x;
    int g = idx >> 14;
    int rem = idx & 16383;
    int n = rem >> 4;
    int d4 = (rem & 15) * 4;
    float l = g_lacc[g * N_ + n] + g_lacc[G * N_ + g * N_ + n];
    float inv = 1.0f / l;
    size_t off = ((size_t)g * N_ + n) * DH + d4;
    float4 o0 = *(const float4*)&g_oacc[off];
    float4 o1 = *(const float4*)&g_oacc[(size_t)G * N_ * DH + off];
    int b = g >> 3, h = g & 7;
    float* dst = g_y + ((size_t)b * N_ + n) * INNER + h * 64 + d4;
    *(float4*)dst = make_float4((o0.x + o1.x) * inv, (o0.y + o1.y) * inv,
                                (o0.z + o1.z) * inv, (o0.w + o1.w) * inv);
}

// ---------------------------------------------------------------------------
// K4: out = y @ W2^T + bias2  (fp16 HMMA, double-buffered)
// ---------------------------------------------------------------------------
__global__ __launch_bounds__(256) void k_out(float* __restrict__ out) {
    __shared__ __half As[2][128 * 40], Bs[2][128 * 40];
    const int t = threadIdx.x, warp = t >> 5, lane = t & 31;
    const int g8 = lane >> 2, t4 = lane & 3;
    const int n0 = blockIdx.x * 128, m0 = blockIdx.y * 128;
    float acc[4][4][4] = {};
    R4T ra, rb;
    ldg4(ra, g_y + (size_t)m0 * INNER, INNER);
    ldg4(rb, g_w2 + (size_t)n0 * INNER, INNER);
    sts4h<40, 0>(As[0], ra, 1.f);
    sts4h<40, 0>(Bs[0], rb, 1.f);
    __syncthreads();
    int cur = 0;
    for (int k0 = 32; k0 < INNER; k0 += 32) {
        ldg4(ra, g_y + (size_t)m0 * INNER + k0, INNER);
        ldg4(rb, g_w2 + (size_t)n0 * INNER + k0, INNER);
        mma_h<4, 4, 4, 2, 40, 40>(As[cur], Bs[cur], warp, g8, t4, acc);
        sts4h<40, 0>(As[cur ^ 1], ra, 1.f);
        sts4h<40, 0>(Bs[cur ^ 1], rb, 1.f);
        __syncthreads();
        cur ^= 1;
    }
    mma_h<4, 4, 4, 2, 40, 40>(As[cur], Bs[cur], warp, g8, t4, acc);
    const int wm = warp >> 2, wn = warp & 3;
#pragma unroll
    for (int mt = 0; mt < 4; mt++)
#pragma unroll
        for (int nt = 0; nt < 4; nt++) {
            int col = n0 + wn * 32 + nt * 8 + 2 * t4;
            float b0 = g_b2[col], b1 = g_b2[col + 1];
            int r = m0 + wm * 64 + mt * 16 + g8;
            *(float2*)&out[(size_t)r * DIM + col] =
                make_float2(acc[mt][nt][0] + b0, acc[mt][nt][1] + b1);
            *(float2*)&out[(size_t)(r + 8) * DIM + col] =
                make_float2(acc[mt][nt][2] + b0, acc[mt][nt][3] + b1);
        }
}

// ---------------------------------------------------------------------------
// Precompute: W2 = Wout(.,h-block) @ Wm ; bias2 = b_out + Wout b_merge~
// ---------------------------------------------------------------------------
__global__ __launch_bounds__(256) void k_w2(const float* __restrict__ w_merge,
                                            const float* __restrict__ w_out) {
    __shared__ float wm[64 * 64];
    const int t = threadIdx.x;
    for (int i = t; i < 4096; i += 256) wm[i] = w_merge[i];
    __syncthreads();
    int idx = blockIdx.x * 256 + t;
    int c = idx >> 9, i = idx & 511;
    int h = i >> 6, d = i & 63;
    const float* wo = w_out + (size_t)c * INNER + h * 64;
    float s = 0.f;
#pragma unroll 8
    for (int dp = 0; dp < 64; dp++) s += wo[dp] * wm[dp * 64 + d];
    g_w2[idx] = s;
}

__global__ __launch_bounds__(256) void k_bias2(const float* __restrict__ w_out,
                                               const float* __restrict__ b_merge,
                                               const float* __restrict__ b_out) {
    int c = blockIdx.x * 8 + (threadIdx.x >> 5);
    int lane = threadIdx.x & 31;
    float s = 0.f;
    for (int i = lane; i < INNER; i += 32)
        s += w_out[(size_t)c * INNER + i] * b_merge[i & 63];
    for (int o = 16; o; o >>= 1) s += __shfl_xor_sync(~0u, s, o);
    if (lane == 0) g_b2[c] = b_out[c] + s;
}

__global__ __launch_bounds__(256) void k_copy(const float* __restrict__ src,
                                              float* __restrict__ dst, int n4) {
    int i = blockIdx.x * blockDim.x + threadIdx.x;
    if (i < n4) ((float4*)dst)[i] = ((const float4*)src)[i];
}

extern "C" void kernel_launch(void* const* d_in, const int* in_sizes, int n_in,
                              void* d_out, int out_size) {
    const float* x       = (const float*)d_in[0];
    const float* lidar   = (const float*)d_in[1];
    const float* w_qkv   = (const float*)d_in[2];
    const float* w_merge = (const float*)d_in[3];
    const float* b_merge = (const float*)d_in[4];
    const float* w_out   = (const float*)d_in[5];
    const float* b_out   = (const float*)d_in[6];
    const float* conv_w  = (const float*)d_in[7];
    float* out = (float*)d_out;

    const int flashSmem = 62976 * 2 + (3 * 128 + 512) * 4;   // ~129.5 KB
    const int lstatsSmem = 27648 * 2 + (128 + 512) * 4;      // ~57.9 KB
    cudaFuncSetAttribute(k_flash, cudaFuncAttributeMaxDynamicSharedMemorySize,
                         flashSmem);
    cudaFuncSetAttribute(k_lstats, cudaFuncAttributeMaxDynamicSharedMemorySize,
                         lstatsSmem);

    // launch order keeps k_flash 4th (ncu captures launch #4)
    k_qkv<<<dim3(12, 64), 256>>>(x, w_qkv);
    k_bounds<<<dim3(G, 2), 256>>>(conv_w, lidar);
    k_lstats<<<dim3(8, G), 256, lstatsSmem>>>(lidar);
    k_flash<<<dim3(8, G, 2), 256, flashSmem>>>(lidar, conv_w);
    k_w2<<<1024, 256>>>(w_merge, w_out);
    k_bias2<<<64, 256>>>(w_out, b_merge, b_out);
    k_combine<<<4096, 256>>>();
    k_out<<<dim3(4, 64), 256>>>(out);

    const int outElems = B_ * N_ * DIM;
    if (out_size >= 2 * outElems)
        k_copy<<<(outElems / 4 + 255) / 256, 256>>>(lidar, out + outElems,
                                                    outElems / 4);
}